// round 5
// baseline (speedup 1.0000x reference)
#include <cuda_runtime.h>
#include <math.h>

#define H 1024
#define V 50257
#define S 4096

#define AB 148                         /* attention blocks (all wave-1 resident) */
#define NLOGH ((V + 15) / 16)          /* 3142 logits_h blocks (16 rows each) */
#define GRID_A (AB + NLOGH)
#define LOGB ((V + 15) / 16)           /* kernel B blocks */
#define AWARPS (AB * 16)               /* 2368 attention warps */

// -------- scratch (device globals; zero-initialized) --------
__device__ float  g_gates[4 * H];
__device__ float  g_h[H];
__device__ float  g_v[H];
__device__ float  g_vpart[AB * H];
__device__ float  g_scores[S];
__device__ float  g_sm_m, g_sm_inv;
__device__ float  g_cpart[AB * H];
__device__ float  g_feat[2 * H];
__device__ float  g_logits[V];
__device__ float2 g_lsepart[LOGB];
__device__ float  g_lse;
__device__ unsigned g_bar_cnt[8];      // wraps each use
__device__ unsigned g_bar_gen[8];      // monotonic across replays
__device__ int      g_hflag;           // set in kernel A, reset by kernel B last block
__device__ unsigned g_cntB;            // kernel B last-block counter (wraps)

// grid barrier among the AB attention blocks (gen-based, replay-safe)
__device__ __forceinline__ void gridbar(int idx) {
    __syncthreads();
    if (threadIdx.x == 0) {
        __threadfence();
        volatile unsigned* genp = (volatile unsigned*)&g_bar_gen[idx];
        unsigned g = *genp;
        unsigned old = atomicInc(&g_bar_cnt[idx], AB - 1);
        if (old == AB - 1) {
            atomicAdd(&g_bar_gen[idx], 1u);
        } else {
            while (*genp == g) __nanosleep(64);
        }
        __threadfence();
    }
    __syncthreads();
}

// warp dot of a 1024-float row (global) with a 1024-float smem vector.
// Batched 8x float4 loads (MLP=8), then FMA, then shfl tree.
__device__ __forceinline__ float dot1024(const float4* __restrict__ wrow,
                                         const float4* __restrict__ svec,
                                         int lane) {
    float4 e[8];
#pragma unroll
    for (int k = 0; k < 8; ++k) e[k] = wrow[lane + 32 * k];
    float acc = 0.f;
#pragma unroll
    for (int k = 0; k < 8; ++k) {
        float4 b = svec[lane + 32 * k];
        acc += e[k].x * b.x + e[k].y * b.y + e[k].z * b.z + e[k].w * b.w;
    }
#pragma unroll
    for (int o = 16; o; o >>= 1) acc += __shfl_xor_sync(0xffffffffu, acc, o);
    return acc;
}

// float4 add helper
__device__ __forceinline__ void f4add(float4& a, const float4& b) {
    a.x += b.x; a.y += b.y; a.z += b.z; a.w += b.w;
}

// ====================== KERNEL A ======================
// bids [0,148): attention pipeline with grid barriers.
// bids [148, GRID_A): logits h-half (out_W[:, :H] @ h), gated on g_hflag.
__global__ __launch_bounds__(512, 2)
void kA(const int* __restrict__ word,
        const float* __restrict__ emb,
        const float* __restrict__ h0,
        const float* __restrict__ c0,
        const float* __restrict__ Wih,
        const float* __restrict__ Whh,
        const float* __restrict__ bih,
        const float* __restrict__ bhh,
        const float* __restrict__ attnW,
        const float* __restrict__ enc,
        const float* __restrict__ outW,
        const float* __restrict__ outb,
        float* __restrict__ out_h,
        float* __restrict__ out_c,
        float* __restrict__ out_attn) {
    __shared__ float sA[H];
    __shared__ float sB[H];
    __shared__ float sw[28];
    __shared__ float sred[512];

    int tid  = threadIdx.x;
    int lane = tid & 31;
    int warp = tid >> 5;
    int bid  = blockIdx.x;

    if (bid >= AB) {
        // ---------- logits_h block ----------
        if (tid == 0) {
            volatile int* f = &g_hflag;
            while (*f == 0) __nanosleep(128);
            __threadfence();
        }
        __syncthreads();
        for (int i = tid; i < H; i += 512) sA[i] = g_h[i];
        __syncthreads();
        int row = (bid - AB) * 16 + warp;
        if (row < V) {
            float d = dot1024((const float4*)(outW + (size_t)row * (2 * H)),
                              (const float4*)sA, lane);
            if (lane == 0) g_logits[row] = d + outb[row];
        }
        return;
    }

    // ---------- attention block ----------
    int gwarp = bid * 16 + warp;           // 0..2367

    // P1: gates.  sA=x (embedding row), sB=h0.
    {
        int w = word[0];
        for (int i = tid; i < H; i += 512) {
            sA[i] = emb[(size_t)w * H + i];
            sB[i] = h0[i];
        }
        __syncthreads();
        for (int r = gwarp; r < 4 * H; r += AWARPS) {
            float d1 = dot1024((const float4*)(Wih + (size_t)r * H), (const float4*)sA, lane);
            float d2 = dot1024((const float4*)(Whh + (size_t)r * H), (const float4*)sB, lane);
            if (lane == 0) g_gates[r] = d1 + d2 + bih[r] + bhh[r];
        }
    }
    gridbar(0);

    // P2: LSTM pointwise (block 0 only), then publish h-flag.
    if (bid == 0) {
        for (int j = tid; j < H; j += 512) {
            float ig = g_gates[j];
            float fg = g_gates[H + j];
            float gg = g_gates[2 * H + j];
            float og = g_gates[3 * H + j];
            float si = 1.f / (1.f + expf(-ig));
            float sf = 1.f / (1.f + expf(-fg));
            float so = 1.f / (1.f + expf(-og));
            float cn = sf * c0[j] + si * tanhf(gg);
            float hn = so * tanhf(cn);
            g_h[j] = hn;
            g_feat[j] = hn;
            out_h[j] = hn;
            out_c[j] = cn;
        }
        __syncthreads();
        if (tid == 0) {
            __threadfence();
            g_hflag = 1;       // releases the logits_h blocks
        }
    }
    gridbar(1);

    // load h into sB for vpart
    for (int i = tid; i < H; i += 512) sB[i] = g_h[i];
    __syncthreads();

    // P3: vpart — block handles j = bid + 148k (k<7); thread owns float2 cols.
    {
        const float2* aw2 = (const float2*)attnW;
        float2 e[7]; float hv[7];
#pragma unroll
        for (int k = 0; k < 7; ++k) {
            int j = bid + AB * k;
            if (j < H) { e[k] = aw2[(size_t)j * (H / 2) + tid]; hv[k] = sB[j]; }
            else       { e[k] = make_float2(0.f, 0.f);          hv[k] = 0.f; }
        }
        float2 acc = make_float2(0.f, 0.f);
#pragma unroll
        for (int k = 0; k < 7; ++k) { acc.x += e[k].x * hv[k]; acc.y += e[k].y * hv[k]; }
        ((float2*)(g_vpart + (size_t)bid * H))[tid] = acc;
    }
    gridbar(2);

    // P4: v reduce — warp aw handles float4 chunk c=aw (c<256).
    if (gwarp < H / 4) {
        int c = gwarp;
        const float4* vp4 = (const float4*)g_vpart;
        float4 a = make_float4(0.f, 0.f, 0.f, 0.f);
#pragma unroll
        for (int q = 0; q < 5; ++q) {
            int p = lane + 32 * q;
            if (p < AB) f4add(a, vp4[(size_t)p * (H / 4) + c]);
        }
#pragma unroll
        for (int o = 16; o; o >>= 1) {
            a.x += __shfl_xor_sync(0xffffffffu, a.x, o);
            a.y += __shfl_xor_sync(0xffffffffu, a.y, o);
            a.z += __shfl_xor_sync(0xffffffffu, a.z, o);
            a.w += __shfl_xor_sync(0xffffffffu, a.w, o);
        }
        if (lane == 0) ((float4*)g_v)[c] = a;
    }
    gridbar(3);

    // P5: scores — warp per row; v in sA.
    for (int i = tid; i < H; i += 512) sA[i] = g_v[i];
    __syncthreads();
    for (int r = gwarp; r < S; r += AWARPS) {
        float d = dot1024((const float4*)(enc + (size_t)r * H), (const float4*)sA, lane);
        if (lane == 0) g_scores[r] = d;
    }
    gridbar(4);

    // P5.5: softmax stats (block 0 only).
    if (bid == 0) {
        float x[8];
#pragma unroll
        for (int k = 0; k < 8; ++k) x[k] = g_scores[tid + 512 * k];
        float m = x[0];
#pragma unroll
        for (int k = 1; k < 8; ++k) m = fmaxf(m, x[k]);
        sred[tid] = m;
        __syncthreads();
        for (int o = 256; o; o >>= 1) {
            if (tid < o) sred[tid] = fmaxf(sred[tid], sred[tid + o]);
            __syncthreads();
        }
        m = sred[0];
        __syncthreads();
        float s = 0.f;
#pragma unroll
        for (int k = 0; k < 8; ++k) s += expf(x[k] - m);
        sred[tid] = s;
        __syncthreads();
        for (int o = 256; o; o >>= 1) {
            if (tid < o) sred[tid] += sred[tid + o];
            __syncthreads();
        }
        if (tid == 0) { g_sm_m = m; g_sm_inv = 1.f / sred[0]; }
    }
    gridbar(5);

    // P6: context partials — block handles s = bid + 148k (k<28).
    {
        float m = g_sm_m, inv = g_sm_inv;
        if (tid < 28) {
            int s = bid + AB * tid;
            if (s < S) {
                float a = expf(g_scores[s] - m) * inv;
                sw[tid] = a;
                out_attn[s] = a;
            } else sw[tid] = 0.f;
        }
        __syncthreads();
        const float2* e2b = (const float2*)enc;
        float2 acc = make_float2(0.f, 0.f);
#pragma unroll
        for (int grp = 0; grp < 4; ++grp) {
            float2 e[7]; float wv[7];
#pragma unroll
            for (int k = 0; k < 7; ++k) {
                int kk = grp * 7 + k;
                int s  = bid + AB * kk;
                if (s < S) { e[k] = e2b[(size_t)s * (H / 2) + tid]; wv[k] = sw[kk]; }
                else       { e[k] = make_float2(0.f, 0.f);          wv[k] = 0.f; }
            }
#pragma unroll
            for (int k = 0; k < 7; ++k) { acc.x += e[k].x * wv[k]; acc.y += e[k].y * wv[k]; }
        }
        ((float2*)(g_cpart + (size_t)bid * H))[tid] = acc;
    }
    gridbar(6);

    // P7: context reduce -> g_feat[H:2H) — warp per float4 chunk.
    if (gwarp < H / 4) {
        int c = gwarp;
        const float4* cp4 = (const float4*)g_cpart;
        float4 a = make_float4(0.f, 0.f, 0.f, 0.f);
#pragma unroll
        for (int q = 0; q < 5; ++q) {
            int p = lane + 32 * q;
            if (p < AB) f4add(a, cp4[(size_t)p * (H / 4) + c]);
        }
#pragma unroll
        for (int o = 16; o; o >>= 1) {
            a.x += __shfl_xor_sync(0xffffffffu, a.x, o);
            a.y += __shfl_xor_sync(0xffffffffu, a.y, o);
            a.z += __shfl_xor_sync(0xffffffffu, a.z, o);
            a.w += __shfl_xor_sync(0xffffffffu, a.w, o);
        }
        if (lane == 0) ((float4*)g_feat)[(H / 4) + c] = a;
    }
    // kernel end orders everything for kernel B
}

// ====================== KERNEL B ======================
// logits c-half accumulate + LSE partials; last block merges + resets hflag.
__global__ __launch_bounds__(512, 2)
void kB(const float* __restrict__ outW) {
    __shared__ float sC[H];
    __shared__ float swarp[16];
    __shared__ bool  s_last;
    int tid  = threadIdx.x;
    int lane = tid & 31;
    int warp = tid >> 5;
    for (int i = tid; i < H; i += 512) sC[i] = g_feat[H + i];
    __syncthreads();
    int row = blockIdx.x * 16 + warp;
    float val = -INFINITY;
    if (row < V) {
        float d = dot1024((const float4*)(outW + (size_t)row * (2 * H) + H),
                          (const float4*)sC, lane);
        if (lane == 0) {
            val = g_logits[row] + d;
            g_logits[row] = val;
        }
    }
    if (lane == 0) swarp[warp] = val;
    __syncthreads();
    if (tid == 0) {
        float m = swarp[0];
#pragma unroll
        for (int i = 1; i < 16; ++i) m = fmaxf(m, swarp[i]);
        float s = 0.f;
#pragma unroll
        for (int i = 0; i < 16; ++i) s += expf(swarp[i] - m);   // exp(-inf-m)=0
        g_lsepart[blockIdx.x] = make_float2(m, s);
    }
    __threadfence();
    __syncthreads();
    if (tid == 0) {
        unsigned c = atomicInc(&g_cntB, LOGB - 1);
        s_last = (c == LOGB - 1);
    }
    __syncthreads();
    if (s_last) {
        __shared__ float rm[512];
        __shared__ float rs[512];
        float m = -INFINITY, s = 0.f;
        for (int i = tid; i < LOGB; i += 512) {   // fixed order per thread
            float2 p = g_lsepart[i];
            float mn = fmaxf(m, p.x);
            s = s * expf(m - mn) + p.y * expf(p.x - mn);
            m = mn;
        }
        rm[tid] = m; rs[tid] = s;
        __syncthreads();
        for (int o = 256; o; o >>= 1) {
            if (tid < o) {
                float m2 = rm[tid + o], s2 = rs[tid + o];
                float mn = fmaxf(rm[tid], m2);
                rs[tid] = rs[tid] * expf(rm[tid] - mn) + s2 * expf(m2 - mn);
                rm[tid] = mn;
            }
            __syncthreads();
        }
        if (tid == 0) {
            g_lse = rm[0] + logf(rs[0]);
            g_hflag = 0;                 // reset for next replay
        }
    }
}

// ====================== KERNEL C ======================
__global__ void kC(float* __restrict__ out) {
    int t = blockIdx.x * 256 + threadIdx.x;
    if (t < V) out[t] = g_logits[t] - g_lse;
}

extern "C" void kernel_launch(void* const* d_in, const int* in_sizes, int n_in,
                              void* d_out, int out_size) {
    const int*   word   = (const int*)  d_in[0];
    const float* h0     = (const float*)d_in[1];
    const float* c0     = (const float*)d_in[2];
    const float* enc    = (const float*)d_in[3];
    const float* emb    = (const float*)d_in[4];
    const float* Wih    = (const float*)d_in[5];
    const float* Whh    = (const float*)d_in[6];
    const float* bih    = (const float*)d_in[7];
    const float* bhh    = (const float*)d_in[8];
    const float* attnW  = (const float*)d_in[9];
    /* attnb (d_in[10]) unused: softmax shift-invariance */
    const float* outW   = (const float*)d_in[11];
    const float* outb   = (const float*)d_in[12];

    float* out = (float*)d_out;
    float* o_logsm = out;
    float* o_h     = out + V;
    float* o_c     = out + V + H;
    float* o_attn  = out + V + 2 * H;

    kA<<<GRID_A, 512>>>(word, emb, h0, c0, Wih, Whh, bih, bhh,
                        attnW, enc, outW, outb, o_h, o_c, o_attn);
    kB<<<LOGB, 512>>>(outW);
    kC<<<(V + 255) / 256, 256>>>(o_logsm);
}

// round 6
// speedup vs baseline: 1.2310x; 1.2310x over previous
#include <cuda_runtime.h>
#include <math.h>

#define H 1024
#define V 50257
#define S 4096

#define GATES_BLOCKS  512
#define VPART_BLOCKS  32
#define SCORES_BLOCKS 512
#define CPART_BLOCKS  128
#define LOGITS_BLOCKS 296              /* persistent: 2 per SM */
#define LOGITS_WARPS  (LOGITS_BLOCKS * 8)

// -------- scratch (device globals; zero-initialized) --------
__device__ float  g_gates[4 * H];
__device__ float  g_h[H];
__device__ float  g_vpart[VPART_BLOCKS * H];
__device__ float  g_v[H];
__device__ float  g_scores[S];
__device__ float2 g_smpart[SCORES_BLOCKS];
__device__ float  g_sm_m, g_sm_inv;
__device__ float  g_cpart[CPART_BLOCKS * H];
__device__ float  g_feat[2 * H];
__device__ float  g_logits[V];
__device__ float2 g_lsepart[LOGITS_BLOCKS];
__device__ float  g_lse;
__device__ unsigned g_cnt0, g_cnt1, g_cnt2, g_cnt3, g_cnt4;   // zero-init; wrap to 0 each replay

// K1: gates = W_ih·x + W_hh·h0 + biases; last block does the LSTM pointwise.
__global__ void k_gates(const int* __restrict__ word,
                        const float* __restrict__ emb,
                        const float* __restrict__ h0,
                        const float* __restrict__ c0,
                        const float* __restrict__ Wih,
                        const float* __restrict__ Whh,
                        const float* __restrict__ bih,
                        const float* __restrict__ bhh,
                        float* __restrict__ out_h,
                        float* __restrict__ out_c) {
    __shared__ float sx[H];
    __shared__ float sh[H];
    __shared__ bool  s_last;
    int tid = threadIdx.x;
    int w = word[0];
    for (int i = tid; i < H; i += 256) {
        sx[i] = emb[(size_t)w * H + i];
        sh[i] = h0[i];
    }
    __syncthreads();
    int lane = tid & 31;
    int warp = tid >> 5;
    int row  = blockIdx.x * 8 + warp;   // < 4096 always
    const float4* wi = (const float4*)(Wih + (size_t)row * H) + lane;
    const float4* wh = (const float4*)(Whh + (size_t)row * H) + lane;
    const float4* x4 = (const float4*)sx + lane;
    const float4* h4 = (const float4*)sh + lane;
    float4 ea[8], eb[8];
#pragma unroll
    for (int k = 0; k < 8; ++k) { ea[k] = wi[32 * k]; eb[k] = wh[32 * k]; }
    float acc = 0.f;
#pragma unroll
    for (int k = 0; k < 8; ++k) {
        float4 b = x4[32 * k], d = h4[32 * k];
        acc += ea[k].x * b.x + ea[k].y * b.y + ea[k].z * b.z + ea[k].w * b.w;
        acc += eb[k].x * d.x + eb[k].y * d.y + eb[k].z * d.z + eb[k].w * d.w;
    }
#pragma unroll
    for (int o = 16; o; o >>= 1) acc += __shfl_xor_sync(0xffffffffu, acc, o);
    if (lane == 0) g_gates[row] = acc + bih[row] + bhh[row];

    __threadfence();
    __syncthreads();
    if (tid == 0) {
        unsigned t = atomicInc(&g_cnt0, GATES_BLOCKS - 1);
        s_last = (t == GATES_BLOCKS - 1);
    }
    __syncthreads();
    if (s_last) {
        for (int j = tid; j < H; j += 256) {
            float ig = g_gates[j];
            float fg = g_gates[H + j];
            float gg = g_gates[2 * H + j];
            float og = g_gates[3 * H + j];
            float si = 1.f / (1.f + expf(-ig));
            float sf = 1.f / (1.f + expf(-fg));
            float so = 1.f / (1.f + expf(-og));
            float cn = sf * c0[j] + si * tanhf(gg);
            float hn = so * tanhf(cn);
            g_h[j] = hn;
            g_feat[j] = hn;
            out_h[j] = hn;
            out_c[j] = cn;
        }
    }
}

// K2: v[k] = sum_j attn_W[j][k] * h[j].  grid 32 x 1024.
__global__ void k_vpart(const float* __restrict__ attnW) {
    __shared__ float  shh[32];
    __shared__ float4 spart[1024];
    __shared__ bool   s_last;
    int t = threadIdx.x;
    int c = t & 255;     // column chunk 0..255
    int g = t >> 8;      // row group 0..3
    int j0 = blockIdx.x * 32;
    if (t < 32) shh[t] = g_h[j0 + t];
    __syncthreads();
    const float4* base = (const float4*)attnW + (size_t)(j0 + g * 8) * (H / 4) + c;
    float4 e[8];
#pragma unroll
    for (int r = 0; r < 8; ++r) e[r] = base[(size_t)r * (H / 4)];
    float4 acc = make_float4(0.f, 0.f, 0.f, 0.f);
#pragma unroll
    for (int r = 0; r < 8; ++r) {
        float hv = shh[g * 8 + r];
        acc.x += e[r].x * hv; acc.y += e[r].y * hv;
        acc.z += e[r].z * hv; acc.w += e[r].w * hv;
    }
    spart[t] = acc;
    __syncthreads();
    if (g == 0) {
        float4 a = spart[c], b = spart[256 + c], d = spart[512 + c], f = spart[768 + c];
        a.x += b.x + d.x + f.x; a.y += b.y + d.y + f.y;
        a.z += b.z + d.z + f.z; a.w += b.w + d.w + f.w;
        ((float4*)(g_vpart + (size_t)blockIdx.x * H))[c] = a;
    }
    __threadfence();
    __syncthreads();
    if (t == 0) {
        unsigned cnt = atomicInc(&g_cnt1, VPART_BLOCKS - 1);
        s_last = (cnt == VPART_BLOCKS - 1);
    }
    __syncthreads();
    if (s_last) {
        const float4* p4 = (const float4*)g_vpart;
        float4 a = make_float4(0.f, 0.f, 0.f, 0.f);
#pragma unroll
        for (int b = 0; b < 8; ++b) {
            float4 e2 = p4[(size_t)(g * 8 + b) * (H / 4) + c];
            a.x += e2.x; a.y += e2.y; a.z += e2.z; a.w += e2.w;
        }
        spart[t] = a;
        __syncthreads();
        if (g == 0) {
            float4 x = spart[c], y = spart[256 + c], z = spart[512 + c], u = spart[768 + c];
            x.x += y.x + z.x + u.x; x.y += y.y + z.y + u.y;
            x.z += y.z + z.z + u.z; x.w += y.w + z.w + u.w;
            ((float4*)g_v)[c] = x;
        }
    }
}

// K3: scores[s] = enc[s]·v; per-block softmax partials; last block merges.
__global__ void k_scores(const float* __restrict__ enc) {
    __shared__ float sv[H];
    __shared__ float swarp[8];
    __shared__ bool  s_last;
    int tid = threadIdx.x;
    for (int i = tid; i < H; i += 256) sv[i] = g_v[i];
    __syncthreads();
    int lane = tid & 31;
    int warp = tid >> 5;
    int srow = blockIdx.x * 8 + warp;   // < 4096 always
    const float4* e4 = (const float4*)(enc + (size_t)srow * H) + lane;
    const float4* v4 = (const float4*)sv + lane;
    float4 e[8];
#pragma unroll
    for (int k = 0; k < 8; ++k) e[k] = e4[32 * k];
    float acc = 0.f;
#pragma unroll
    for (int k = 0; k < 8; ++k) {
        float4 b = v4[32 * k];
        acc += e[k].x * b.x + e[k].y * b.y + e[k].z * b.z + e[k].w * b.w;
    }
#pragma unroll
    for (int o = 16; o; o >>= 1) acc += __shfl_xor_sync(0xffffffffu, acc, o);
    if (lane == 0) { g_scores[srow] = acc; swarp[warp] = acc; }
    __syncthreads();
    if (tid == 0) {
        float m = swarp[0];
#pragma unroll
        for (int i = 1; i < 8; ++i) m = fmaxf(m, swarp[i]);
        float s = 0.f;
#pragma unroll
        for (int i = 0; i < 8; ++i) s += expf(swarp[i] - m);
        g_smpart[blockIdx.x] = make_float2(m, s);
    }
    __threadfence();
    __syncthreads();
    if (tid == 0) {
        unsigned c = atomicInc(&g_cnt2, SCORES_BLOCKS - 1);
        s_last = (c == SCORES_BLOCKS - 1);
    }
    __syncthreads();
    if (s_last) {
        __shared__ float rm[256];
        __shared__ float rs[256];
        float2 p0 = g_smpart[tid];
        float2 p1 = g_smpart[tid + 256];
        float m = fmaxf(p0.x, p1.x);
        float s = p0.y * expf(p0.x - m) + p1.y * expf(p1.x - m);
        rm[tid] = m; rs[tid] = s;
        __syncthreads();
        for (int o = 128; o; o >>= 1) {
            if (tid < o) {
                float m2 = rm[tid + o], s2 = rs[tid + o];
                float mn = fmaxf(rm[tid], m2);
                rs[tid] = rs[tid] * expf(rm[tid] - mn) + s2 * expf(m2 - mn);
                rm[tid] = mn;
            }
            __syncthreads();
        }
        if (tid == 0) { g_sm_m = rm[0]; g_sm_inv = 1.f / rs[0]; }
    }
}

// K4: attn normalize + context partials.  grid 128 x 1024.
__global__ void k_cpart(const float* __restrict__ enc,
                        float* __restrict__ out_attn) {
    __shared__ float  sat[32];
    __shared__ float4 spart[1024];
    __shared__ bool   s_last;
    int t = threadIdx.x;
    int c = t & 255;
    int g = t >> 8;
    int s0 = blockIdx.x * 32;
    if (t < 32) {
        float a = expf(g_scores[s0 + t] - g_sm_m) * g_sm_inv;
        sat[t] = a;
        out_attn[s0 + t] = a;
    }
    __syncthreads();
    const float4* base = (const float4*)enc + (size_t)(s0 + g * 8) * (H / 4) + c;
    float4 e[8];
#pragma unroll
    for (int r = 0; r < 8; ++r) e[r] = base[(size_t)r * (H / 4)];
    float4 acc = make_float4(0.f, 0.f, 0.f, 0.f);
#pragma unroll
    for (int r = 0; r < 8; ++r) {
        float aw = sat[g * 8 + r];
        acc.x += e[r].x * aw; acc.y += e[r].y * aw;
        acc.z += e[r].z * aw; acc.w += e[r].w * aw;
    }
    spart[t] = acc;
    __syncthreads();
    if (g == 0) {
        float4 a = spart[c], b = spart[256 + c], d = spart[512 + c], f = spart[768 + c];
        a.x += b.x + d.x + f.x; a.y += b.y + d.y + f.y;
        a.z += b.z + d.z + f.z; a.w += b.w + d.w + f.w;
        ((float4*)(g_cpart + (size_t)blockIdx.x * H))[c] = a;
    }
    __threadfence();
    __syncthreads();
    if (t == 0) {
        unsigned cnt = atomicInc(&g_cnt3, CPART_BLOCKS - 1);
        s_last = (cnt == CPART_BLOCKS - 1);
    }
    __syncthreads();
    if (s_last) {
        const float4* p4 = (const float4*)g_cpart;
        float4 a = make_float4(0.f, 0.f, 0.f, 0.f);
#pragma unroll 8
        for (int b = 0; b < 32; ++b) {
            float4 e2 = p4[(size_t)(g * 32 + b) * (H / 4) + c];
            a.x += e2.x; a.y += e2.y; a.z += e2.z; a.w += e2.w;
        }
        spart[t] = a;
        __syncthreads();
        if (g == 0) {
            float4 x = spart[c], y = spart[256 + c], z = spart[512 + c], u = spart[768 + c];
            x.x += y.x + z.x + u.x; x.y += y.y + z.y + u.y;
            x.z += y.z + z.z + u.z; x.w += y.w + z.w + u.w;
            ((float4*)g_feat)[(H / 4) + c] = x;
        }
    }
}

// K5: logits = out_W·feat + out_b — PERSISTENT grid-stride version.
// 296 blocks x 256 thr; each block loads feat once; warp loops rows.
// Per-warp online (m,s) LSE accumulation; 296 partials; last block merges.
__global__ __launch_bounds__(256, 2)
void k_logits(const float* __restrict__ outW,
              const float* __restrict__ outb) {
    __shared__ float  sf[2 * H];
    __shared__ float2 swarp[8];
    __shared__ bool   s_last;
    int tid  = threadIdx.x;
    int lane = tid & 31;
    int warp = tid >> 5;
    for (int i = tid; i < 2 * H; i += 256) sf[i] = g_feat[i];
    __syncthreads();
    const float4* f4 = (const float4*)sf + lane;

    float wm = -INFINITY, ws = 0.f;   // per-warp (lane0-valid) online LSE
    for (int row = blockIdx.x * 8 + warp; row < V; row += LOGITS_WARPS) {
        const float4* w4 = (const float4*)(outW + (size_t)row * (2 * H)) + lane;
        float4 e[16];
#pragma unroll
        for (int k = 0; k < 16; ++k) e[k] = w4[32 * k];
        float acc = 0.f;
#pragma unroll
        for (int k = 0; k < 16; ++k) {
            float4 b = f4[32 * k];
            acc += e[k].x * b.x + e[k].y * b.y + e[k].z * b.z + e[k].w * b.w;
        }
#pragma unroll
        for (int o = 16; o; o >>= 1) acc += __shfl_xor_sync(0xffffffffu, acc, o);
        if (lane == 0) {
            float val = acc + outb[row];
            g_logits[row] = val;
            float mn = fmaxf(wm, val);
            ws = ws * expf(wm - mn) + expf(val - mn);
            wm = mn;
        }
    }
    if (lane == 0) swarp[warp] = make_float2(wm, ws);
    __syncthreads();
    if (tid == 0) {
        float m = -INFINITY, s = 0.f;
#pragma unroll
        for (int i = 0; i < 8; ++i) {
            float2 p = swarp[i];
            float mn = fmaxf(m, p.x);
            s = s * expf(m - mn) + p.y * expf(p.x - mn);
            m = mn;
        }
        g_lsepart[blockIdx.x] = make_float2(m, s);
    }
    __threadfence();
    __syncthreads();
    if (tid == 0) {
        unsigned c = atomicInc(&g_cnt4, LOGITS_BLOCKS - 1);
        s_last = (c == LOGITS_BLOCKS - 1);
    }
    __syncthreads();
    if (s_last) {
        __shared__ float rm[256];
        __shared__ float rs[256];
        float m = -INFINITY, s = 0.f;
        for (int i = tid; i < LOGITS_BLOCKS; i += 256) {   // fixed order per thread
            float2 p = g_lsepart[i];
            float mn = fmaxf(m, p.x);
            s = s * expf(m - mn) + p.y * expf(p.x - mn);
            m = mn;
        }
        rm[tid] = m; rs[tid] = s;
        __syncthreads();
        for (int o = 128; o; o >>= 1) {
            if (tid < o) {
                float m2 = rm[tid + o], s2 = rs[tid + o];
                float mn = fmaxf(rm[tid], m2);
                rs[tid] = rs[tid] * expf(rm[tid] - mn) + s2 * expf(m2 - mn);
                rm[tid] = mn;
            }
            __syncthreads();
        }
        if (tid == 0) g_lse = rm[0] + logf(rs[0]);
    }
}

// K6: final log-softmax write.
__global__ void k_final(float* __restrict__ out) {
    int t = blockIdx.x * 512 + threadIdx.x;
    if (t < V) out[t] = g_logits[t] - g_lse;
}

extern "C" void kernel_launch(void* const* d_in, const int* in_sizes, int n_in,
                              void* d_out, int out_size) {
    const int*   word   = (const int*)  d_in[0];
    const float* h0     = (const float*)d_in[1];
    const float* c0     = (const float*)d_in[2];
    const float* enc    = (const float*)d_in[3];
    const float* emb    = (const float*)d_in[4];
    const float* Wih    = (const float*)d_in[5];
    const float* Whh    = (const float*)d_in[6];
    const float* bih    = (const float*)d_in[7];
    const float* bhh    = (const float*)d_in[8];
    const float* attnW  = (const float*)d_in[9];
    /* attnb (d_in[10]) unused: softmax shift-invariance */
    const float* outW   = (const float*)d_in[11];
    const float* outb   = (const float*)d_in[12];

    float* out = (float*)d_out;
    float* o_logsm = out;
    float* o_h     = out + V;
    float* o_c     = out + V + H;
    float* o_attn  = out + V + 2 * H;

    k_gates <<<GATES_BLOCKS, 256>>>(word, emb, h0, c0, Wih, Whh, bih, bhh, o_h, o_c);
    k_vpart <<<VPART_BLOCKS, 1024>>>(attnW);
    k_scores<<<SCORES_BLOCKS, 256>>>(enc);
    k_cpart <<<CPART_BLOCKS, 1024>>>(enc, o_attn);
    k_logits<<<LOGITS_BLOCKS, 256>>>(outW, outb);
    k_final <<<(V + 511) / 512, 512>>>(o_logsm);
}

// round 7
// speedup vs baseline: 1.2352x; 1.0033x over previous
#include <cuda_runtime.h>
#include <math.h>

#define H 1024
#define V 50257
#define S 4096

#define GATES_BLOCKS  512
#define VPART_BLOCKS  32
#define SCORES_BLOCKS 512
#define CPART_BLOCKS  128
#define LOGITS_BLOCKS 296              /* persistent: 2 per SM */
#define LOGITS_WARPS  (LOGITS_BLOCKS * 8)

// -------- scratch (device globals; zero-initialized) --------
__device__ float  g_gates[4 * H];
__device__ float  g_h[H];
__device__ float  g_vpart[VPART_BLOCKS * H];
__device__ float  g_v[H];
__device__ float  g_scores[S];
__device__ float2 g_smpart[SCORES_BLOCKS];
__device__ float  g_sm_m, g_sm_inv;
__device__ float  g_cpart[CPART_BLOCKS * H];
__device__ float  g_feat[2 * H];
__device__ float  g_logits[V];
__device__ float2 g_lsepart[LOGITS_BLOCKS];
__device__ float  g_lse;
__device__ unsigned g_cnt0, g_cnt1, g_cnt2, g_cnt3, g_cnt4;   // zero-init; wrap to 0 each replay

// K1: gates = W_ih·x + W_hh·h0 + biases; last block does the LSTM pointwise.
__global__ void k_gates(const int* __restrict__ word,
                        const float* __restrict__ emb,
                        const float* __restrict__ h0,
                        const float* __restrict__ c0,
                        const float* __restrict__ Wih,
                        const float* __restrict__ Whh,
                        const float* __restrict__ bih,
                        const float* __restrict__ bhh,
                        float* __restrict__ out_h,
                        float* __restrict__ out_c) {
    __shared__ float sx[H];
    __shared__ float sh[H];
    __shared__ bool  s_last;
    int tid = threadIdx.x;
    int w = word[0];
    for (int i = tid; i < H; i += 256) {
        sx[i] = emb[(size_t)w * H + i];
        sh[i] = h0[i];
    }
    __syncthreads();
    int lane = tid & 31;
    int warp = tid >> 5;
    int row  = blockIdx.x * 8 + warp;   // < 4096 always
    const float4* wi = (const float4*)(Wih + (size_t)row * H) + lane;
    const float4* wh = (const float4*)(Whh + (size_t)row * H) + lane;
    const float4* x4 = (const float4*)sx + lane;
    const float4* h4 = (const float4*)sh + lane;
    float4 ea[8], eb[8];
#pragma unroll
    for (int k = 0; k < 8; ++k) { ea[k] = wi[32 * k]; eb[k] = wh[32 * k]; }
    float acc = 0.f;
#pragma unroll
    for (int k = 0; k < 8; ++k) {
        float4 b = x4[32 * k], d = h4[32 * k];
        acc += ea[k].x * b.x + ea[k].y * b.y + ea[k].z * b.z + ea[k].w * b.w;
        acc += eb[k].x * d.x + eb[k].y * d.y + eb[k].z * d.z + eb[k].w * d.w;
    }
#pragma unroll
    for (int o = 16; o; o >>= 1) acc += __shfl_xor_sync(0xffffffffu, acc, o);
    if (lane == 0) g_gates[row] = acc + bih[row] + bhh[row];

    __threadfence();
    __syncthreads();
    if (tid == 0) {
        unsigned t = atomicInc(&g_cnt0, GATES_BLOCKS - 1);
        s_last = (t == GATES_BLOCKS - 1);
    }
    __syncthreads();
    if (s_last) {
        for (int j = tid; j < H; j += 256) {
            float ig = g_gates[j];
            float fg = g_gates[H + j];
            float gg = g_gates[2 * H + j];
            float og = g_gates[3 * H + j];
            float si = 1.f / (1.f + expf(-ig));
            float sf = 1.f / (1.f + expf(-fg));
            float so = 1.f / (1.f + expf(-og));
            float cn = sf * c0[j] + si * tanhf(gg);
            float hn = so * tanhf(cn);
            g_h[j] = hn;
            g_feat[j] = hn;
            out_h[j] = hn;
            out_c[j] = cn;
        }
    }
}

// K2: v[k] = sum_j attn_W[j][k] * h[j].  grid 32 x 1024.
__global__ __launch_bounds__(1024, 1)
void k_vpart(const float* __restrict__ attnW) {
    __shared__ float  shh[32];
    __shared__ float4 spart[1024];
    __shared__ bool   s_last;
    int t = threadIdx.x;
    int c = t & 255;     // column chunk 0..255
    int g = t >> 8;      // row group 0..3
    int j0 = blockIdx.x * 32;
    if (t < 32) shh[t] = g_h[j0 + t];
    __syncthreads();
    const float4* base = (const float4*)attnW + (size_t)(j0 + g * 8) * (H / 4) + c;
    float4 e[8];
#pragma unroll
    for (int r = 0; r < 8; ++r) e[r] = base[(size_t)r * (H / 4)];
    float4 acc = make_float4(0.f, 0.f, 0.f, 0.f);
#pragma unroll
    for (int r = 0; r < 8; ++r) {
        float hv = shh[g * 8 + r];
        acc.x += e[r].x * hv; acc.y += e[r].y * hv;
        acc.z += e[r].z * hv; acc.w += e[r].w * hv;
    }
    spart[t] = acc;
    __syncthreads();
    if (g == 0) {
        float4 a = spart[c], b = spart[256 + c], d = spart[512 + c], f = spart[768 + c];
        a.x += b.x + d.x + f.x; a.y += b.y + d.y + f.y;
        a.z += b.z + d.z + f.z; a.w += b.w + d.w + f.w;
        ((float4*)(g_vpart + (size_t)blockIdx.x * H))[c] = a;
    }
    __threadfence();
    __syncthreads();
    if (t == 0) {
        unsigned cnt = atomicInc(&g_cnt1, VPART_BLOCKS - 1);
        s_last = (cnt == VPART_BLOCKS - 1);
    }
    __syncthreads();
    if (s_last) {
        const float4* p4 = (const float4*)g_vpart;
        float4 a = make_float4(0.f, 0.f, 0.f, 0.f);
#pragma unroll
        for (int b = 0; b < 8; ++b) {
            float4 e2 = p4[(size_t)(g * 8 + b) * (H / 4) + c];
            a.x += e2.x; a.y += e2.y; a.z += e2.z; a.w += e2.w;
        }
        spart[t] = a;
        __syncthreads();
        if (g == 0) {
            float4 x = spart[c], y = spart[256 + c], z = spart[512 + c], u = spart[768 + c];
            x.x += y.x + z.x + u.x; x.y += y.y + z.y + u.y;
            x.z += y.z + z.z + u.z; x.w += y.w + z.w + u.w;
            ((float4*)g_v)[c] = x;
        }
    }
}

// K3: scores[s] = enc[s]·v; per-block softmax partials; last block merges.
__global__ void k_scores(const float* __restrict__ enc) {
    __shared__ float sv[H];
    __shared__ float swarp[8];
    __shared__ bool  s_last;
    int tid = threadIdx.x;
    for (int i = tid; i < H; i += 256) sv[i] = g_v[i];
    __syncthreads();
    int lane = tid & 31;
    int warp = tid >> 5;
    int srow = blockIdx.x * 8 + warp;   // < 4096 always
    const float4* e4 = (const float4*)(enc + (size_t)srow * H) + lane;
    const float4* v4 = (const float4*)sv + lane;
    float4 e[8];
#pragma unroll
    for (int k = 0; k < 8; ++k) e[k] = e4[32 * k];
    float acc = 0.f;
#pragma unroll
    for (int k = 0; k < 8; ++k) {
        float4 b = v4[32 * k];
        acc += e[k].x * b.x + e[k].y * b.y + e[k].z * b.z + e[k].w * b.w;
    }
#pragma unroll
    for (int o = 16; o; o >>= 1) acc += __shfl_xor_sync(0xffffffffu, acc, o);
    if (lane == 0) { g_scores[srow] = acc; swarp[warp] = acc; }
    __syncthreads();
    if (tid == 0) {
        float m = swarp[0];
#pragma unroll
        for (int i = 1; i < 8; ++i) m = fmaxf(m, swarp[i]);
        float s = 0.f;
#pragma unroll
        for (int i = 0; i < 8; ++i) s += expf(swarp[i] - m);
        g_smpart[blockIdx.x] = make_float2(m, s);
    }
    __threadfence();
    __syncthreads();
    if (tid == 0) {
        unsigned c = atomicInc(&g_cnt2, SCORES_BLOCKS - 1);
        s_last = (c == SCORES_BLOCKS - 1);
    }
    __syncthreads();
    if (s_last) {
        __shared__ float rm[256];
        __shared__ float rs[256];
        float2 p0 = g_smpart[tid];
        float2 p1 = g_smpart[tid + 256];
        float m = fmaxf(p0.x, p1.x);
        float s = p0.y * expf(p0.x - m) + p1.y * expf(p1.x - m);
        rm[tid] = m; rs[tid] = s;
        __syncthreads();
        for (int o = 128; o; o >>= 1) {
            if (tid < o) {
                float m2 = rm[tid + o], s2 = rs[tid + o];
                float mn = fmaxf(rm[tid], m2);
                rs[tid] = rs[tid] * expf(rm[tid] - mn) + s2 * expf(m2 - mn);
                rm[tid] = mn;
            }
            __syncthreads();
        }
        if (tid == 0) { g_sm_m = rm[0]; g_sm_inv = 1.f / rs[0]; }
    }
}

// K4: attn normalize + context partials.  grid 128 x 1024.
__global__ __launch_bounds__(1024, 1)
void k_cpart(const float* __restrict__ enc,
             float* __restrict__ out_attn) {
    __shared__ float  sat[32];
    __shared__ float4 spart[1024];
    __shared__ bool   s_last;
    int t = threadIdx.x;
    int c = t & 255;
    int g = t >> 8;
    int s0 = blockIdx.x * 32;
    if (t < 32) {
        float a = expf(g_scores[s0 + t] - g_sm_m) * g_sm_inv;
        sat[t] = a;
        out_attn[s0 + t] = a;
    }
    __syncthreads();
    const float4* base = (const float4*)enc + (size_t)(s0 + g * 8) * (H / 4) + c;
    float4 e[8];
#pragma unroll
    for (int r = 0; r < 8; ++r) e[r] = base[(size_t)r * (H / 4)];
    float4 acc = make_float4(0.f, 0.f, 0.f, 0.f);
#pragma unroll
    for (int r = 0; r < 8; ++r) {
        float aw = sat[g * 8 + r];
        acc.x += e[r].x * aw; acc.y += e[r].y * aw;
        acc.z += e[r].z * aw; acc.w += e[r].w * aw;
    }
    spart[t] = acc;
    __syncthreads();
    if (g == 0) {
        float4 a = spart[c], b = spart[256 + c], d = spart[512 + c], f = spart[768 + c];
        a.x += b.x + d.x + f.x; a.y += b.y + d.y + f.y;
        a.z += b.z + d.z + f.z; a.w += b.w + d.w + f.w;
        ((float4*)(g_cpart + (size_t)blockIdx.x * H))[c] = a;
    }
    __threadfence();
    __syncthreads();
    if (t == 0) {
        unsigned cnt = atomicInc(&g_cnt3, CPART_BLOCKS - 1);
        s_last = (cnt == CPART_BLOCKS - 1);
    }
    __syncthreads();
    if (s_last) {
        const float4* p4 = (const float4*)g_cpart;
        float4 a = make_float4(0.f, 0.f, 0.f, 0.f);
#pragma unroll 8
        for (int b = 0; b < 32; ++b) {
            float4 e2 = p4[(size_t)(g * 32 + b) * (H / 4) + c];
            a.x += e2.x; a.y += e2.y; a.z += e2.z; a.w += e2.w;
        }
        spart[t] = a;
        __syncthreads();
        if (g == 0) {
            float4 x = spart[c], y = spart[256 + c], z = spart[512 + c], u = spart[768 + c];
            x.x += y.x + z.x + u.x; x.y += y.y + z.y + u.y;
            x.z += y.z + z.z + u.z; x.w += y.w + z.w + u.w;
            ((float4*)g_feat)[(H / 4) + c] = x;
        }
    }
}

// K5: logits = out_W·feat + out_b — persistent, TWO-ROW software pipeline.
// Warp interleaves rows (r, r+LOGITS_WARPS) in 8-deep half-batches so one
// row's loads are in flight while the other's reduce runs.
__global__ __launch_bounds__(256, 2)
void k_logits(const float* __restrict__ outW,
              const float* __restrict__ outb) {
    __shared__ float  sf[2 * H];
    __shared__ float2 swarp[8];
    __shared__ bool   s_last;
    int tid  = threadIdx.x;
    int lane = tid & 31;
    int warp = tid >> 5;
    for (int i = tid; i < 2 * H; i += 256) sf[i] = g_feat[i];
    __syncthreads();
    const float4* f4 = (const float4*)sf + lane;

    float wm = -INFINITY, ws = 0.f;   // per-warp (lane0-valid) online LSE
    const int W = LOGITS_WARPS;
    int r = blockIdx.x * 8 + warp;

    while (r + W < V) {               // paired rows r and r+W
        const float4* wa = (const float4*)(outW + (size_t)r       * (2 * H)) + lane;
        const float4* wb = (const float4*)(outW + (size_t)(r + W) * (2 * H)) + lane;
        float4 A[8], B[8];
#pragma unroll
        for (int k = 0; k < 8; ++k) A[k] = wa[32 * k];
#pragma unroll
        for (int k = 0; k < 8; ++k) B[k] = wb[32 * k];
        float accA = 0.f;
#pragma unroll
        for (int k = 0; k < 8; ++k) {
            float4 b = f4[32 * k];
            accA += A[k].x * b.x + A[k].y * b.y + A[k].z * b.z + A[k].w * b.w;
        }
#pragma unroll
        for (int k = 0; k < 8; ++k) A[k] = wa[32 * (k + 8)];
        float accB = 0.f;
#pragma unroll
        for (int k = 0; k < 8; ++k) {
            float4 b = f4[32 * k];
            accB += B[k].x * b.x + B[k].y * b.y + B[k].z * b.z + B[k].w * b.w;
        }
#pragma unroll
        for (int k = 0; k < 8; ++k) B[k] = wb[32 * (k + 8)];
#pragma unroll
        for (int k = 0; k < 8; ++k) {
            float4 b = f4[32 * (k + 8)];
            accA += A[k].x * b.x + A[k].y * b.y + A[k].z * b.z + A[k].w * b.w;
        }
#pragma unroll
        for (int o = 16; o; o >>= 1) accA += __shfl_xor_sync(0xffffffffu, accA, o);
        if (lane == 0) {
            float val = accA + outb[r];
            g_logits[r] = val;
            float mn = fmaxf(wm, val);
            ws = ws * expf(wm - mn) + expf(val - mn);
            wm = mn;
        }
#pragma unroll
        for (int k = 0; k < 8; ++k) {
            float4 b = f4[32 * (k + 8)];
            accB += B[k].x * b.x + B[k].y * b.y + B[k].z * b.z + B[k].w * b.w;
        }
#pragma unroll
        for (int o = 16; o; o >>= 1) accB += __shfl_xor_sync(0xffffffffu, accB, o);
        if (lane == 0) {
            float val = accB + outb[r + W];
            g_logits[r + W] = val;
            float mn = fmaxf(wm, val);
            ws = ws * expf(wm - mn) + expf(val - mn);
            wm = mn;
        }
        r += 2 * W;
    }
    if (r < V) {                      // leftover single row
        const float4* wa = (const float4*)(outW + (size_t)r * (2 * H)) + lane;
        float4 A[16];
#pragma unroll
        for (int k = 0; k < 16; ++k) A[k] = wa[32 * k];
        float acc = 0.f;
#pragma unroll
        for (int k = 0; k < 16; ++k) {
            float4 b = f4[32 * k];
            acc += A[k].x * b.x + A[k].y * b.y + A[k].z * b.z + A[k].w * b.w;
        }
#pragma unroll
        for (int o = 16; o; o >>= 1) acc += __shfl_xor_sync(0xffffffffu, acc, o);
        if (lane == 0) {
            float val = acc + outb[r];
            g_logits[r] = val;
            float mn = fmaxf(wm, val);
            ws = ws * expf(wm - mn) + expf(val - mn);
            wm = mn;
        }
    }

    if (lane == 0) swarp[warp] = make_float2(wm, ws);
    __syncthreads();
    if (tid == 0) {
        float m = -INFINITY, s = 0.f;
#pragma unroll
        for (int i = 0; i < 8; ++i) {
            float2 p = swarp[i];
            float mn = fmaxf(m, p.x);
            s = s * expf(m - mn) + p.y * expf(p.x - mn);
            m = mn;
        }
        g_lsepart[blockIdx.x] = make_float2(m, s);
    }
    __threadfence();
    __syncthreads();
    if (tid == 0) {
        unsigned c = atomicInc(&g_cnt4, LOGITS_BLOCKS - 1);
        s_last = (c == LOGITS_BLOCKS - 1);
    }
    __syncthreads();
    if (s_last) {
        __shared__ float rm[256];
        __shared__ float rs[256];
        float m = -INFINITY, s = 0.f;
        for (int i = tid; i < LOGITS_BLOCKS; i += 256) {   // fixed order per thread
            float2 p = g_lsepart[i];
            float mn = fmaxf(m, p.x);
            s = s * expf(m - mn) + p.y * expf(p.x - mn);
            m = mn;
        }
        rm[tid] = m; rs[tid] = s;
        __syncthreads();
        for (int o = 128; o; o >>= 1) {
            if (tid < o) {
                float m2 = rm[tid + o], s2 = rs[tid + o];
                float mn = fmaxf(rm[tid], m2);
                rs[tid] = rs[tid] * expf(rm[tid] - mn) + s2 * expf(m2 - mn);
                rm[tid] = mn;
            }
            __syncthreads();
        }
        if (tid == 0) g_lse = rm[0] + logf(rs[0]);
    }
}

// K6: final log-softmax write (float4; V = 4*12564 + 1).
__global__ void k_final(float* __restrict__ out) {
    int t = blockIdx.x * 256 + threadIdx.x;
    float lse = g_lse;
    if (t < V / 4) {
        float4 v = ((const float4*)g_logits)[t];
        v.x -= lse; v.y -= lse; v.z -= lse; v.w -= lse;
        ((float4*)out)[t] = v;
    }
    if (t == 0) out[V - 1] = g_logits[V - 1] - lse;
}

extern "C" void kernel_launch(void* const* d_in, const int* in_sizes, int n_in,
                              void* d_out, int out_size) {
    const int*   word   = (const int*)  d_in[0];
    const float* h0     = (const float*)d_in[1];
    const float* c0     = (const float*)d_in[2];
    const float* enc    = (const float*)d_in[3];
    const float* emb    = (const float*)d_in[4];
    const float* Wih    = (const float*)d_in[5];
    const float* Whh    = (const float*)d_in[6];
    const float* bih    = (const float*)d_in[7];
    const float* bhh    = (const float*)d_in[8];
    const float* attnW  = (const float*)d_in[9];
    /* attnb (d_in[10]) unused: softmax shift-invariance */
    const float* outW   = (const float*)d_in[11];
    const float* outb   = (const float*)d_in[12];

    float* out = (float*)d_out;
    float* o_logsm = out;
    float* o_h     = out + V;
    float* o_c     = out + V + H;
    float* o_attn  = out + V + 2 * H;

    k_gates <<<GATES_BLOCKS, 256>>>(word, emb, h0, c0, Wih, Whh, bih, bhh, o_h, o_c);
    k_vpart <<<VPART_BLOCKS, 1024>>>(attnW);
    k_scores<<<SCORES_BLOCKS, 256>>>(enc);
    k_cpart <<<CPART_BLOCKS, 1024>>>(enc, o_attn);
    k_logits<<<LOGITS_BLOCKS, 256>>>(outW, outb);
    k_final <<<(V / 4 + 255) / 256, 256>>>(o_logsm);
}

// round 8
// speedup vs baseline: 1.2450x; 1.0080x over previous
#include <cuda_runtime.h>
#include <math.h>

#define H 1024
#define V 50257
#define S 4096

#define GATES_BLOCKS  512
#define VPART_BLOCKS  32
#define SCORES_BLOCKS 512
#define CPART_BLOCKS  128
#define LOGITS_BLOCKS 296              /* persistent: 2 per SM */
#define LOGITS_WARPS  (LOGITS_BLOCKS * 8)

// -------- scratch (device globals; zero-initialized) --------
__device__ float  g_gates[4 * H];
__device__ float  g_h[H];
__device__ float  g_vpart[VPART_BLOCKS * H];
__device__ float  g_v[H];
__device__ float  g_scores[S];
__device__ float2 g_smpart[SCORES_BLOCKS];
__device__ float  g_sm_m, g_sm_inv;
__device__ float  g_cpart[CPART_BLOCKS * H];
__device__ float  g_feat[2 * H];
__device__ float  g_logits[V];
__device__ float2 g_lsepart[LOGITS_BLOCKS];
__device__ float  g_lse;
__device__ unsigned g_cnt0, g_cnt1, g_cnt2, g_cnt3, g_cnt4;   // zero-init; wrap to 0 each replay

// K1: gates = W_ih·x + W_hh·h0 + biases; last block does the LSTM pointwise.
__global__ void k_gates(const int* __restrict__ word,
                        const float* __restrict__ emb,
                        const float* __restrict__ h0,
                        const float* __restrict__ c0,
                        const float* __restrict__ Wih,
                        const float* __restrict__ Whh,
                        const float* __restrict__ bih,
                        const float* __restrict__ bhh,
                        float* __restrict__ out_h,
                        float* __restrict__ out_c) {
    __shared__ float sx[H];
    __shared__ float sh[H];
    __shared__ bool  s_last;
    int tid = threadIdx.x;
    int w = word[0];
    for (int i = tid; i < H; i += 256) {
        sx[i] = emb[(size_t)w * H + i];
        sh[i] = h0[i];
    }
    __syncthreads();
    int lane = tid & 31;
    int warp = tid >> 5;
    int row  = blockIdx.x * 8 + warp;   // < 4096 always
    const float4* wi = (const float4*)(Wih + (size_t)row * H) + lane;
    const float4* wh = (const float4*)(Whh + (size_t)row * H) + lane;
    const float4* x4 = (const float4*)sx + lane;
    const float4* h4 = (const float4*)sh + lane;
    float4 ea[8], eb[8];
#pragma unroll
    for (int k = 0; k < 8; ++k) { ea[k] = wi[32 * k]; eb[k] = wh[32 * k]; }
    float acc = 0.f;
#pragma unroll
    for (int k = 0; k < 8; ++k) {
        float4 b = x4[32 * k], d = h4[32 * k];
        acc += ea[k].x * b.x + ea[k].y * b.y + ea[k].z * b.z + ea[k].w * b.w;
        acc += eb[k].x * d.x + eb[k].y * d.y + eb[k].z * d.z + eb[k].w * d.w;
    }
#pragma unroll
    for (int o = 16; o; o >>= 1) acc += __shfl_xor_sync(0xffffffffu, acc, o);
    if (lane == 0) g_gates[row] = acc + bih[row] + bhh[row];

    __threadfence();
    __syncthreads();
    if (tid == 0) {
        unsigned t = atomicInc(&g_cnt0, GATES_BLOCKS - 1);
        s_last = (t == GATES_BLOCKS - 1);
    }
    __syncthreads();
    if (s_last) {
        for (int j = tid; j < H; j += 256) {
            float ig = g_gates[j];
            float fg = g_gates[H + j];
            float gg = g_gates[2 * H + j];
            float og = g_gates[3 * H + j];
            float si = 1.f / (1.f + expf(-ig));
            float sf = 1.f / (1.f + expf(-fg));
            float so = 1.f / (1.f + expf(-og));
            float cn = sf * c0[j] + si * tanhf(gg);
            float hn = so * tanhf(cn);
            g_h[j] = hn;
            g_feat[j] = hn;
            out_h[j] = hn;
            out_c[j] = cn;
        }
    }
}

// K2: v[k] = sum_j attn_W[j][k] * h[j].  grid 32 x 1024.
__global__ __launch_bounds__(1024, 1)
void k_vpart(const float* __restrict__ attnW) {
    __shared__ float  shh[32];
    __shared__ float4 spart[1024];
    __shared__ bool   s_last;
    int t = threadIdx.x;
    int c = t & 255;     // column chunk 0..255
    int g = t >> 8;      // row group 0..3
    int j0 = blockIdx.x * 32;
    if (t < 32) shh[t] = g_h[j0 + t];
    __syncthreads();
    const float4* base = (const float4*)attnW + (size_t)(j0 + g * 8) * (H / 4) + c;
    float4 e[8];
#pragma unroll
    for (int r = 0; r < 8; ++r) e[r] = base[(size_t)r * (H / 4)];
    float4 acc = make_float4(0.f, 0.f, 0.f, 0.f);
#pragma unroll
    for (int r = 0; r < 8; ++r) {
        float hv = shh[g * 8 + r];
        acc.x += e[r].x * hv; acc.y += e[r].y * hv;
        acc.z += e[r].z * hv; acc.w += e[r].w * hv;
    }
    spart[t] = acc;
    __syncthreads();
    if (g == 0) {
        float4 a = spart[c], b = spart[256 + c], d = spart[512 + c], f = spart[768 + c];
        a.x += b.x + d.x + f.x; a.y += b.y + d.y + f.y;
        a.z += b.z + d.z + f.z; a.w += b.w + d.w + f.w;
        ((float4*)(g_vpart + (size_t)blockIdx.x * H))[c] = a;
    }
    __threadfence();
    __syncthreads();
    if (t == 0) {
        unsigned cnt = atomicInc(&g_cnt1, VPART_BLOCKS - 1);
        s_last = (cnt == VPART_BLOCKS - 1);
    }
    __syncthreads();
    if (s_last) {
        const float4* p4 = (const float4*)g_vpart;
        float4 a = make_float4(0.f, 0.f, 0.f, 0.f);
#pragma unroll
        for (int b = 0; b < 8; ++b) {
            float4 e2 = p4[(size_t)(g * 8 + b) * (H / 4) + c];
            a.x += e2.x; a.y += e2.y; a.z += e2.z; a.w += e2.w;
        }
        spart[t] = a;
        __syncthreads();
        if (g == 0) {
            float4 x = spart[c], y = spart[256 + c], z = spart[512 + c], u = spart[768 + c];
            x.x += y.x + z.x + u.x; x.y += y.y + z.y + u.y;
            x.z += y.z + z.z + u.z; x.w += y.w + z.w + u.w;
            ((float4*)g_v)[c] = x;
        }
    }
}

// K3: scores[s] = enc[s]·v; per-block softmax partials; last block merges.
__global__ void k_scores(const float* __restrict__ enc) {
    __shared__ float sv[H];
    __shared__ float swarp[8];
    __shared__ bool  s_last;
    int tid = threadIdx.x;
    for (int i = tid; i < H; i += 256) sv[i] = g_v[i];
    __syncthreads();
    int lane = tid & 31;
    int warp = tid >> 5;
    int srow = blockIdx.x * 8 + warp;   // < 4096 always
    const float4* e4 = (const float4*)(enc + (size_t)srow * H) + lane;
    const float4* v4 = (const float4*)sv + lane;
    float4 e[8];
#pragma unroll
    for (int k = 0; k < 8; ++k) e[k] = e4[32 * k];
    float acc = 0.f;
#pragma unroll
    for (int k = 0; k < 8; ++k) {
        float4 b = v4[32 * k];
        acc += e[k].x * b.x + e[k].y * b.y + e[k].z * b.z + e[k].w * b.w;
    }
#pragma unroll
    for (int o = 16; o; o >>= 1) acc += __shfl_xor_sync(0xffffffffu, acc, o);
    if (lane == 0) { g_scores[srow] = acc; swarp[warp] = acc; }
    __syncthreads();
    if (tid == 0) {
        float m = swarp[0];
#pragma unroll
        for (int i = 1; i < 8; ++i) m = fmaxf(m, swarp[i]);
        float s = 0.f;
#pragma unroll
        for (int i = 0; i < 8; ++i) s += expf(swarp[i] - m);
        g_smpart[blockIdx.x] = make_float2(m, s);
    }
    __threadfence();
    __syncthreads();
    if (tid == 0) {
        unsigned c = atomicInc(&g_cnt2, SCORES_BLOCKS - 1);
        s_last = (c == SCORES_BLOCKS - 1);
    }
    __syncthreads();
    if (s_last) {
        __shared__ float rm[256];
        __shared__ float rs[256];
        float2 p0 = g_smpart[tid];
        float2 p1 = g_smpart[tid + 256];
        float m = fmaxf(p0.x, p1.x);
        float s = p0.y * expf(p0.x - m) + p1.y * expf(p1.x - m);
        rm[tid] = m; rs[tid] = s;
        __syncthreads();
        for (int o = 128; o; o >>= 1) {
            if (tid < o) {
                float m2 = rm[tid + o], s2 = rs[tid + o];
                float mn = fmaxf(rm[tid], m2);
                rs[tid] = rs[tid] * expf(rm[tid] - mn) + s2 * expf(m2 - mn);
                rm[tid] = mn;
            }
            __syncthreads();
        }
        if (tid == 0) { g_sm_m = rm[0]; g_sm_inv = 1.f / rs[0]; }
    }
}

// K4: attn normalize + context partials.  grid 128 x 1024.
__global__ __launch_bounds__(1024, 1)
void k_cpart(const float* __restrict__ enc,
             float* __restrict__ out_attn) {
    __shared__ float  sat[32];
    __shared__ float4 spart[1024];
    __shared__ bool   s_last;
    int t = threadIdx.x;
    int c = t & 255;
    int g = t >> 8;
    int s0 = blockIdx.x * 32;
    if (t < 32) {
        float a = expf(g_scores[s0 + t] - g_sm_m) * g_sm_inv;
        sat[t] = a;
        out_attn[s0 + t] = a;
    }
    __syncthreads();
    const float4* base = (const float4*)enc + (size_t)(s0 + g * 8) * (H / 4) + c;
    float4 e[8];
#pragma unroll
    for (int r = 0; r < 8; ++r) e[r] = base[(size_t)r * (H / 4)];
    float4 acc = make_float4(0.f, 0.f, 0.f, 0.f);
#pragma unroll
    for (int r = 0; r < 8; ++r) {
        float aw = sat[g * 8 + r];
        acc.x += e[r].x * aw; acc.y += e[r].y * aw;
        acc.z += e[r].z * aw; acc.w += e[r].w * aw;
    }
    spart[t] = acc;
    __syncthreads();
    if (g == 0) {
        float4 a = spart[c], b = spart[256 + c], d = spart[512 + c], f = spart[768 + c];
        a.x += b.x + d.x + f.x; a.y += b.y + d.y + f.y;
        a.z += b.z + d.z + f.z; a.w += b.w + d.w + f.w;
        ((float4*)(g_cpart + (size_t)blockIdx.x * H))[c] = a;
    }
    __threadfence();
    __syncthreads();
    if (t == 0) {
        unsigned cnt = atomicInc(&g_cnt3, CPART_BLOCKS - 1);
        s_last = (cnt == CPART_BLOCKS - 1);
    }
    __syncthreads();
    if (s_last) {
        const float4* p4 = (const float4*)g_cpart;
        float4 a = make_float4(0.f, 0.f, 0.f, 0.f);
#pragma unroll 8
        for (int b = 0; b < 32; ++b) {
            float4 e2 = p4[(size_t)(g * 32 + b) * (H / 4) + c];
            a.x += e2.x; a.y += e2.y; a.z += e2.z; a.w += e2.w;
        }
        spart[t] = a;
        __syncthreads();
        if (g == 0) {
            float4 x = spart[c], y = spart[256 + c], z = spart[512 + c], u = spart[768 + c];
            x.x += y.x + z.x + u.x; x.y += y.y + z.y + u.y;
            x.z += y.z + z.z + u.z; x.w += y.w + z.w + u.w;
            ((float4*)g_feat)[(H / 4) + c] = x;
        }
    }
}

// K5a: logits h-half: g_logits[r] = out_W[r, 0:H]·h + out_b[r].
// Persistent grid-stride, two rows in flight (MLP=16). Runs on side stream,
// overlapped with the attention chain.
__global__ __launch_bounds__(256, 2)
void k_logits_h(const float* __restrict__ outW,
                const float* __restrict__ outb) {
    __shared__ float sf[H];
    int tid  = threadIdx.x;
    int lane = tid & 31;
    int warp = tid >> 5;
    for (int i = tid; i < H; i += 256) sf[i] = g_h[i];
    __syncthreads();
    const float4* f4 = (const float4*)sf + lane;
    const int W = LOGITS_WARPS;
    int r = blockIdx.x * 8 + warp;
    while (r + W < V) {
        const float4* wa = (const float4*)(outW + (size_t)r       * (2 * H)) + lane;
        const float4* wb = (const float4*)(outW + (size_t)(r + W) * (2 * H)) + lane;
        float4 A[8], B[8];
#pragma unroll
        for (int k = 0; k < 8; ++k) A[k] = wa[32 * k];
#pragma unroll
        for (int k = 0; k < 8; ++k) B[k] = wb[32 * k];
        float accA = 0.f, accB = 0.f;
#pragma unroll
        for (int k = 0; k < 8; ++k) {
            float4 b = f4[32 * k];
            accA += A[k].x * b.x + A[k].y * b.y + A[k].z * b.z + A[k].w * b.w;
            accB += B[k].x * b.x + B[k].y * b.y + B[k].z * b.z + B[k].w * b.w;
        }
#pragma unroll
        for (int o = 16; o; o >>= 1) {
            accA += __shfl_xor_sync(0xffffffffu, accA, o);
            accB += __shfl_xor_sync(0xffffffffu, accB, o);
        }
        if (lane == 0) {
            g_logits[r]     = accA + outb[r];
            g_logits[r + W] = accB + outb[r + W];
        }
        r += 2 * W;
    }
    if (r < V) {
        const float4* wa = (const float4*)(outW + (size_t)r * (2 * H)) + lane;
        float4 A[8];
#pragma unroll
        for (int k = 0; k < 8; ++k) A[k] = wa[32 * k];
        float acc = 0.f;
#pragma unroll
        for (int k = 0; k < 8; ++k) {
            float4 b = f4[32 * k];
            acc += A[k].x * b.x + A[k].y * b.y + A[k].z * b.z + A[k].w * b.w;
        }
#pragma unroll
        for (int o = 16; o; o >>= 1) acc += __shfl_xor_sync(0xffffffffu, acc, o);
        if (lane == 0) g_logits[r] = acc + outb[r];
    }
}

// K5b: logits c-half: g_logits[r] += out_W[r, H:2H]·context; online LSE;
// last block merges 296 partials.
__global__ __launch_bounds__(256, 2)
void k_logits_c(const float* __restrict__ outW) {
    __shared__ float  sf[H];
    __shared__ float2 swarp[8];
    __shared__ bool   s_last;
    int tid  = threadIdx.x;
    int lane = tid & 31;
    int warp = tid >> 5;
    for (int i = tid; i < H; i += 256) sf[i] = g_feat[H + i];
    __syncthreads();
    const float4* f4 = (const float4*)sf + lane;
    const int W = LOGITS_WARPS;
    float wm = -INFINITY, ws = 0.f;   // per-warp (lane0-valid) online LSE
    int r = blockIdx.x * 8 + warp;
    while (r + W < V) {
        const float4* wa = (const float4*)(outW + (size_t)r       * (2 * H) + H) + lane;
        const float4* wb = (const float4*)(outW + (size_t)(r + W) * (2 * H) + H) + lane;
        float4 A[8], B[8];
#pragma unroll
        for (int k = 0; k < 8; ++k) A[k] = wa[32 * k];
#pragma unroll
        for (int k = 0; k < 8; ++k) B[k] = wb[32 * k];
        float accA = 0.f, accB = 0.f;
#pragma unroll
        for (int k = 0; k < 8; ++k) {
            float4 b = f4[32 * k];
            accA += A[k].x * b.x + A[k].y * b.y + A[k].z * b.z + A[k].w * b.w;
            accB += B[k].x * b.x + B[k].y * b.y + B[k].z * b.z + B[k].w * b.w;
        }
#pragma unroll
        for (int o = 16; o; o >>= 1) {
            accA += __shfl_xor_sync(0xffffffffu, accA, o);
            accB += __shfl_xor_sync(0xffffffffu, accB, o);
        }
        if (lane == 0) {
            float vA = g_logits[r] + accA;
            float vB = g_logits[r + W] + accB;
            g_logits[r]     = vA;
            g_logits[r + W] = vB;
            float mn = fmaxf(wm, fmaxf(vA, vB));
            ws = ws * expf(wm - mn) + expf(vA - mn) + expf(vB - mn);
            wm = mn;
        }
        r += 2 * W;
    }
    if (r < V) {
        const float4* wa = (const float4*)(outW + (size_t)r * (2 * H) + H) + lane;
        float4 A[8];
#pragma unroll
        for (int k = 0; k < 8; ++k) A[k] = wa[32 * k];
        float acc = 0.f;
#pragma unroll
        for (int k = 0; k < 8; ++k) {
            float4 b = f4[32 * k];
            acc += A[k].x * b.x + A[k].y * b.y + A[k].z * b.z + A[k].w * b.w;
        }
#pragma unroll
        for (int o = 16; o; o >>= 1) acc += __shfl_xor_sync(0xffffffffu, acc, o);
        if (lane == 0) {
            float v = g_logits[r] + acc;
            g_logits[r] = v;
            float mn = fmaxf(wm, v);
            ws = ws * expf(wm - mn) + expf(v - mn);
            wm = mn;
        }
    }

    if (lane == 0) swarp[warp] = make_float2(wm, ws);
    __syncthreads();
    if (tid == 0) {
        float m = -INFINITY, s = 0.f;
#pragma unroll
        for (int i = 0; i < 8; ++i) {
            float2 p = swarp[i];
            float mn = fmaxf(m, p.x);
            s = s * expf(m - mn) + p.y * expf(p.x - mn);
            m = mn;
        }
        g_lsepart[blockIdx.x] = make_float2(m, s);
    }
    __threadfence();
    __syncthreads();
    if (tid == 0) {
        unsigned c = atomicInc(&g_cnt4, LOGITS_BLOCKS - 1);
        s_last = (c == LOGITS_BLOCKS - 1);
    }
    __syncthreads();
    if (s_last) {
        __shared__ float rm[256];
        __shared__ float rs[256];
        float m = -INFINITY, s = 0.f;
        for (int i = tid; i < LOGITS_BLOCKS; i += 256) {   // fixed order per thread
            float2 p = g_lsepart[i];
            float mn = fmaxf(m, p.x);
            s = s * expf(m - mn) + p.y * expf(p.x - mn);
            m = mn;
        }
        rm[tid] = m; rs[tid] = s;
        __syncthreads();
        for (int o = 128; o; o >>= 1) {
            if (tid < o) {
                float m2 = rm[tid + o], s2 = rs[tid + o];
                float mn = fmaxf(rm[tid], m2);
                rs[tid] = rs[tid] * expf(rm[tid] - mn) + s2 * expf(m2 - mn);
                rm[tid] = mn;
            }
            __syncthreads();
        }
        if (tid == 0) g_lse = rm[0] + logf(rs[0]);
    }
}

// K6: final log-softmax write (float4; V = 4*12564 + 1).
__global__ void k_final(float* __restrict__ out) {
    int t = blockIdx.x * 256 + threadIdx.x;
    float lse = g_lse;
    if (t < V / 4) {
        float4 v = ((const float4*)g_logits)[t];
        v.x -= lse; v.y -= lse; v.z -= lse; v.w -= lse;
        ((float4*)out)[t] = v;
    }
    if (t == 0) out[V - 1] = g_logits[V - 1] - lse;
}

extern "C" void kernel_launch(void* const* d_in, const int* in_sizes, int n_in,
                              void* d_out, int out_size) {
    const int*   word   = (const int*)  d_in[0];
    const float* h0     = (const float*)d_in[1];
    const float* c0     = (const float*)d_in[2];
    const float* enc    = (const float*)d_in[3];
    const float* emb    = (const float*)d_in[4];
    const float* Wih    = (const float*)d_in[5];
    const float* Whh    = (const float*)d_in[6];
    const float* bih    = (const float*)d_in[7];
    const float* bhh    = (const float*)d_in[8];
    const float* attnW  = (const float*)d_in[9];
    /* attnb (d_in[10]) unused: softmax shift-invariance */
    const float* outW   = (const float*)d_in[11];
    const float* outb   = (const float*)d_in[12];

    float* out = (float*)d_out;
    float* o_logsm = out;
    float* o_h     = out + V;
    float* o_c     = out + V + H;
    float* o_attn  = out + V + 2 * H;

    // side stream + fork/join events (host objects; no device allocation)
    cudaStream_t s2;
    cudaStreamCreateWithFlags(&s2, cudaStreamNonBlocking);
    cudaEvent_t eFork, eJoin;
    cudaEventCreateWithFlags(&eFork, cudaEventDisableTiming);
    cudaEventCreateWithFlags(&eJoin, cudaEventDisableTiming);

    k_gates <<<GATES_BLOCKS, 256>>>(word, emb, h0, c0, Wih, Whh, bih, bhh, o_h, o_c);
    cudaEventRecord(eFork, 0);

    // side stream: h-half of the big matvec, overlapped with attention chain
    cudaStreamWaitEvent(s2, eFork, 0);
    k_logits_h<<<LOGITS_BLOCKS, 256, 0, s2>>>(outW, outb);
    cudaEventRecord(eJoin, s2);

    // main stream: attention chain
    k_vpart <<<VPART_BLOCKS, 1024>>>(attnW);
    k_scores<<<SCORES_BLOCKS, 256>>>(enc);
    k_cpart <<<CPART_BLOCKS, 1024>>>(enc, o_attn);

    // join, then c-half + finish
    cudaStreamWaitEvent(0, eJoin, 0);
    k_logits_c<<<LOGITS_BLOCKS, 256>>>(outW);
    k_final <<<(V / 4 + 255) / 256, 256>>>(o_logsm);
}

// round 9
// speedup vs baseline: 1.3148x; 1.0560x over previous
#include <cuda_runtime.h>
#include <math.h>

#define H 1024
#define V 50257
#define S 4096

#define GATES_BLOCKS  512
#define VPART_BLOCKS  32
#define SCORES_BLOCKS 512
#define CPART_BLOCKS  128
#define LOGITS_BLOCKS 444              /* persistent: 3 per SM */
#define LOGITS_WARPS  (LOGITS_BLOCKS * 8)

// -------- scratch (device globals; zero-initialized) --------
__device__ float  g_gates[4 * H];
__device__ float  g_h[H];
__device__ float  g_vpart[VPART_BLOCKS * H];
__device__ float  g_v[H];
__device__ float  g_scores[S];
__device__ float2 g_smpart[SCORES_BLOCKS];
__device__ float  g_sm_m, g_sm_inv;
__device__ float  g_cpart[CPART_BLOCKS * H];
__device__ float  g_feat[2 * H];
__device__ float  g_logits[V];
__device__ float2 g_lsepart[LOGITS_BLOCKS];
__device__ float  g_lse;
__device__ unsigned g_cnt0, g_cnt1, g_cnt2, g_cnt3, g_cnt4;   // zero-init; wrap to 0 each replay

// K1: gates = W_ih·x + W_hh·h0 + biases; last block does the LSTM pointwise.
__global__ void k_gates(const int* __restrict__ word,
                        const float* __restrict__ emb,
                        const float* __restrict__ h0,
                        const float* __restrict__ c0,
                        const float* __restrict__ Wih,
                        const float* __restrict__ Whh,
                        const float* __restrict__ bih,
                        const float* __restrict__ bhh,
                        float* __restrict__ out_h,
                        float* __restrict__ out_c) {
    __shared__ float sx[H];
    __shared__ float sh[H];
    __shared__ bool  s_last;
    int tid = threadIdx.x;
    int w = word[0];
    for (int i = tid; i < H; i += 256) {
        sx[i] = emb[(size_t)w * H + i];
        sh[i] = h0[i];
    }
    __syncthreads();
    int lane = tid & 31;
    int warp = tid >> 5;
    int row  = blockIdx.x * 8 + warp;   // < 4096 always
    const float4* wi = (const float4*)(Wih + (size_t)row * H) + lane;
    const float4* wh = (const float4*)(Whh + (size_t)row * H) + lane;
    const float4* x4 = (const float4*)sx + lane;
    const float4* h4 = (const float4*)sh + lane;
    float4 ea[8], eb[8];
#pragma unroll
    for (int k = 0; k < 8; ++k) { ea[k] = __ldcs(wi + 32 * k); eb[k] = __ldcs(wh + 32 * k); }
    float acc = 0.f;
#pragma unroll
    for (int k = 0; k < 8; ++k) {
        float4 b = x4[32 * k], d = h4[32 * k];
        acc += ea[k].x * b.x + ea[k].y * b.y + ea[k].z * b.z + ea[k].w * b.w;
        acc += eb[k].x * d.x + eb[k].y * d.y + eb[k].z * d.z + eb[k].w * d.w;
    }
#pragma unroll
    for (int o = 16; o; o >>= 1) acc += __shfl_xor_sync(0xffffffffu, acc, o);
    if (lane == 0) g_gates[row] = acc + bih[row] + bhh[row];

    __threadfence();
    __syncthreads();
    if (tid == 0) {
        unsigned t = atomicInc(&g_cnt0, GATES_BLOCKS - 1);
        s_last = (t == GATES_BLOCKS - 1);
    }
    __syncthreads();
    if (s_last) {
        for (int j = tid; j < H; j += 256) {
            float ig = g_gates[j];
            float fg = g_gates[H + j];
            float gg = g_gates[2 * H + j];
            float og = g_gates[3 * H + j];
            float si = 1.f / (1.f + expf(-ig));
            float sf = 1.f / (1.f + expf(-fg));
            float so = 1.f / (1.f + expf(-og));
            float cn = sf * c0[j] + si * tanhf(gg);
            float hn = so * tanhf(cn);
            g_h[j] = hn;
            g_feat[j] = hn;
            out_h[j] = hn;
            out_c[j] = cn;
        }
    }
}

// K2: v[k] = sum_j attn_W[j][k] * h[j].  grid 32 x 1024.
__global__ __launch_bounds__(1024, 1)
void k_vpart(const float* __restrict__ attnW) {
    __shared__ float  shh[32];
    __shared__ float4 spart[1024];
    __shared__ bool   s_last;
    int t = threadIdx.x;
    int c = t & 255;     // column chunk 0..255
    int g = t >> 8;      // row group 0..3
    int j0 = blockIdx.x * 32;
    if (t < 32) shh[t] = g_h[j0 + t];
    __syncthreads();
    const float4* base = (const float4*)attnW + (size_t)(j0 + g * 8) * (H / 4) + c;
    float4 e[8];
#pragma unroll
    for (int r = 0; r < 8; ++r) e[r] = base[(size_t)r * (H / 4)];
    float4 acc = make_float4(0.f, 0.f, 0.f, 0.f);
#pragma unroll
    for (int r = 0; r < 8; ++r) {
        float hv = shh[g * 8 + r];
        acc.x += e[r].x * hv; acc.y += e[r].y * hv;
        acc.z += e[r].z * hv; acc.w += e[r].w * hv;
    }
    spart[t] = acc;
    __syncthreads();
    if (g == 0) {
        float4 a = spart[c], b = spart[256 + c], d = spart[512 + c], f = spart[768 + c];
        a.x += b.x + d.x + f.x; a.y += b.y + d.y + f.y;
        a.z += b.z + d.z + f.z; a.w += b.w + d.w + f.w;
        ((float4*)(g_vpart + (size_t)blockIdx.x * H))[c] = a;
    }
    __threadfence();
    __syncthreads();
    if (t == 0) {
        unsigned cnt = atomicInc(&g_cnt1, VPART_BLOCKS - 1);
        s_last = (cnt == VPART_BLOCKS - 1);
    }
    __syncthreads();
    if (s_last) {
        const float4* p4 = (const float4*)g_vpart;
        float4 a = make_float4(0.f, 0.f, 0.f, 0.f);
#pragma unroll
        for (int b = 0; b < 8; ++b) {
            float4 e2 = p4[(size_t)(g * 8 + b) * (H / 4) + c];
            a.x += e2.x; a.y += e2.y; a.z += e2.z; a.w += e2.w;
        }
        spart[t] = a;
        __syncthreads();
        if (g == 0) {
            float4 x = spart[c], y = spart[256 + c], z = spart[512 + c], u = spart[768 + c];
            x.x += y.x + z.x + u.x; x.y += y.y + z.y + u.y;
            x.z += y.z + z.z + u.z; x.w += y.w + z.w + u.w;
            ((float4*)g_v)[c] = x;
        }
    }
}

// K3: scores[s] = enc[s]·v; per-block softmax partials; last block merges.
__global__ void k_scores(const float* __restrict__ enc) {
    __shared__ float sv[H];
    __shared__ float swarp[8];
    __shared__ bool  s_last;
    int tid = threadIdx.x;
    for (int i = tid; i < H; i += 256) sv[i] = g_v[i];
    __syncthreads();
    int lane = tid & 31;
    int warp = tid >> 5;
    int srow = blockIdx.x * 8 + warp;   // < 4096 always
    const float4* e4 = (const float4*)(enc + (size_t)srow * H) + lane;
    const float4* v4 = (const float4*)sv + lane;
    float4 e[8];
#pragma unroll
    for (int k = 0; k < 8; ++k) e[k] = e4[32 * k];
    float acc = 0.f;
#pragma unroll
    for (int k = 0; k < 8; ++k) {
        float4 b = v4[32 * k];
        acc += e[k].x * b.x + e[k].y * b.y + e[k].z * b.z + e[k].w * b.w;
    }
#pragma unroll
    for (int o = 16; o; o >>= 1) acc += __shfl_xor_sync(0xffffffffu, acc, o);
    if (lane == 0) { g_scores[srow] = acc; swarp[warp] = acc; }
    __syncthreads();
    if (tid == 0) {
        float m = swarp[0];
#pragma unroll
        for (int i = 1; i < 8; ++i) m = fmaxf(m, swarp[i]);
        float s = 0.f;
#pragma unroll
        for (int i = 0; i < 8; ++i) s += expf(swarp[i] - m);
        g_smpart[blockIdx.x] = make_float2(m, s);
    }
    __threadfence();
    __syncthreads();
    if (tid == 0) {
        unsigned c = atomicInc(&g_cnt2, SCORES_BLOCKS - 1);
        s_last = (c == SCORES_BLOCKS - 1);
    }
    __syncthreads();
    if (s_last) {
        __shared__ float rm[256];
        __shared__ float rs[256];
        float2 p0 = g_smpart[tid];
        float2 p1 = g_smpart[tid + 256];
        float m = fmaxf(p0.x, p1.x);
        float s = p0.y * expf(p0.x - m) + p1.y * expf(p1.x - m);
        rm[tid] = m; rs[tid] = s;
        __syncthreads();
        for (int o = 128; o; o >>= 1) {
            if (tid < o) {
                float m2 = rm[tid + o], s2 = rs[tid + o];
                float mn = fmaxf(rm[tid], m2);
                rs[tid] = rs[tid] * expf(rm[tid] - mn) + s2 * expf(m2 - mn);
                rm[tid] = mn;
            }
            __syncthreads();
        }
        if (tid == 0) { g_sm_m = rm[0]; g_sm_inv = 1.f / rs[0]; }
    }
}

// K4: attn normalize + context partials.  grid 128 x 1024.
__global__ __launch_bounds__(1024, 1)
void k_cpart(const float* __restrict__ enc,
             float* __restrict__ out_attn) {
    __shared__ float  sat[32];
    __shared__ float4 spart[1024];
    __shared__ bool   s_last;
    int t = threadIdx.x;
    int c = t & 255;
    int g = t >> 8;
    int s0 = blockIdx.x * 32;
    if (t < 32) {
        float a = expf(g_scores[s0 + t] - g_sm_m) * g_sm_inv;
        sat[t] = a;
        out_attn[s0 + t] = a;
    }
    __syncthreads();
    const float4* base = (const float4*)enc + (size_t)(s0 + g * 8) * (H / 4) + c;
    float4 e[8];
#pragma unroll
    for (int r = 0; r < 8; ++r) e[r] = base[(size_t)r * (H / 4)];
    float4 acc = make_float4(0.f, 0.f, 0.f, 0.f);
#pragma unroll
    for (int r = 0; r < 8; ++r) {
        float aw = sat[g * 8 + r];
        acc.x += e[r].x * aw; acc.y += e[r].y * aw;
        acc.z += e[r].z * aw; acc.w += e[r].w * aw;
    }
    spart[t] = acc;
    __syncthreads();
    if (g == 0) {
        float4 a = spart[c], b = spart[256 + c], d = spart[512 + c], f = spart[768 + c];
        a.x += b.x + d.x + f.x; a.y += b.y + d.y + f.y;
        a.z += b.z + d.z + f.z; a.w += b.w + d.w + f.w;
        ((float4*)(g_cpart + (size_t)blockIdx.x * H))[c] = a;
    }
    __threadfence();
    __syncthreads();
    if (t == 0) {
        unsigned cnt = atomicInc(&g_cnt3, CPART_BLOCKS - 1);
        s_last = (cnt == CPART_BLOCKS - 1);
    }
    __syncthreads();
    if (s_last) {
        const float4* p4 = (const float4*)g_cpart;
        float4 a = make_float4(0.f, 0.f, 0.f, 0.f);
#pragma unroll 8
        for (int b = 0; b < 32; ++b) {
            float4 e2 = p4[(size_t)(g * 32 + b) * (H / 4) + c];
            a.x += e2.x; a.y += e2.y; a.z += e2.z; a.w += e2.w;
        }
        spart[t] = a;
        __syncthreads();
        if (g == 0) {
            float4 x = spart[c], y = spart[256 + c], z = spart[512 + c], u = spart[768 + c];
            x.x += y.x + z.x + u.x; x.y += y.y + z.y + u.y;
            x.z += y.z + z.z + u.z; x.w += y.w + z.w + u.w;
            ((float4*)g_feat)[(H / 4) + c] = x;
        }
    }
}

// K5a: logits h-half: g_logits[r] = out_W[r, 0:H]·h + out_b[r].
// Persistent grid-stride, 3 blocks/SM, 16-deep streaming loads.
__global__ __launch_bounds__(256, 3)
void k_logits_h(const float* __restrict__ outW,
                const float* __restrict__ outb) {
    __shared__ float sf[H];
    int tid  = threadIdx.x;
    int lane = tid & 31;
    int warp = tid >> 5;
    for (int i = tid; i < H; i += 256) sf[i] = g_h[i];
    __syncthreads();
    const float4* f4 = (const float4*)sf + lane;
    for (int r = blockIdx.x * 8 + warp; r < V; r += LOGITS_WARPS) {
        const float4* wa = (const float4*)(outW + (size_t)r * (2 * H)) + lane;
        float4 A[8];
#pragma unroll
        for (int k = 0; k < 8; ++k) A[k] = __ldcs(wa + 32 * k);
        float acc = 0.f;
#pragma unroll
        for (int k = 0; k < 8; ++k) {
            float4 b = f4[32 * k];
            acc += A[k].x * b.x + A[k].y * b.y + A[k].z * b.z + A[k].w * b.w;
        }
#pragma unroll
        for (int o = 16; o; o >>= 1) acc += __shfl_xor_sync(0xffffffffu, acc, o);
        if (lane == 0) g_logits[r] = acc + outb[r];
    }
}

// K5b: logits c-half: g_logits[r] += out_W[r, H:2H]·context; online LSE;
// last block merges LOGITS_BLOCKS partials.
__global__ __launch_bounds__(256, 3)
void k_logits_c(const float* __restrict__ outW) {
    __shared__ float  sf[H];
    __shared__ float2 swarp[8];
    __shared__ bool   s_last;
    int tid  = threadIdx.x;
    int lane = tid & 31;
    int warp = tid >> 5;
    for (int i = tid; i < H; i += 256) sf[i] = g_feat[H + i];
    __syncthreads();
    const float4* f4 = (const float4*)sf + lane;
    float wm = -INFINITY, ws = 0.f;   // per-warp (lane0-valid) online LSE
    for (int r = blockIdx.x * 8 + warp; r < V; r += LOGITS_WARPS) {
        const float4* wa = (const float4*)(outW + (size_t)r * (2 * H) + H) + lane;
        float4 A[8];
#pragma unroll
        for (int k = 0; k < 8; ++k) A[k] = __ldcs(wa + 32 * k);
        float acc = 0.f;
#pragma unroll
        for (int k = 0; k < 8; ++k) {
            float4 b = f4[32 * k];
            acc += A[k].x * b.x + A[k].y * b.y + A[k].z * b.z + A[k].w * b.w;
        }
#pragma unroll
        for (int o = 16; o; o >>= 1) acc += __shfl_xor_sync(0xffffffffu, acc, o);
        if (lane == 0) {
            float v = g_logits[r] + acc;
            g_logits[r] = v;
            float mn = fmaxf(wm, v);
            ws = ws * expf(wm - mn) + expf(v - mn);
            wm = mn;
        }
    }

    if (lane == 0) swarp[warp] = make_float2(wm, ws);
    __syncthreads();
    if (tid == 0) {
        float m = -INFINITY, s = 0.f;
#pragma unroll
        for (int i = 0; i < 8; ++i) {
            float2 p = swarp[i];
            float mn = fmaxf(m, p.x);
            s = s * expf(m - mn) + p.y * expf(p.x - mn);
            m = mn;
        }
        g_lsepart[blockIdx.x] = make_float2(m, s);
    }
    __threadfence();
    __syncthreads();
    if (tid == 0) {
        unsigned c = atomicInc(&g_cnt4, LOGITS_BLOCKS - 1);
        s_last = (c == LOGITS_BLOCKS - 1);
    }
    __syncthreads();
    if (s_last) {
        __shared__ float rm[256];
        __shared__ float rs[256];
        float m = -INFINITY, s = 0.f;
        for (int i = tid; i < LOGITS_BLOCKS; i += 256) {   // fixed order per thread
            float2 p = g_lsepart[i];
            float mn = fmaxf(m, p.x);
            s = s * expf(m - mn) + p.y * expf(p.x - mn);
            m = mn;
        }
        rm[tid] = m; rs[tid] = s;
        __syncthreads();
        for (int o = 128; o; o >>= 1) {
            if (tid < o) {
                float m2 = rm[tid + o], s2 = rs[tid + o];
                float mn = fmaxf(rm[tid], m2);
                rs[tid] = rs[tid] * expf(rm[tid] - mn) + s2 * expf(m2 - mn);
                rm[tid] = mn;
            }
            __syncthreads();
        }
        if (tid == 0) g_lse = rm[0] + logf(rs[0]);
    }
}

// K6: final log-softmax write (float4; V = 4*12564 + 1).
__global__ void k_final(float* __restrict__ out) {
    int t = blockIdx.x * 256 + threadIdx.x;
    float lse = g_lse;
    if (t < V / 4) {
        float4 v = ((const float4*)g_logits)[t];
        v.x -= lse; v.y -= lse; v.z -= lse; v.w -= lse;
        ((float4*)out)[t] = v;
    }
    if (t == 0) out[V - 1] = g_logits[V - 1] - lse;
}

extern "C" void kernel_launch(void* const* d_in, const int* in_sizes, int n_in,
                              void* d_out, int out_size) {
    const int*   word   = (const int*)  d_in[0];
    const float* h0     = (const float*)d_in[1];
    const float* c0     = (const float*)d_in[2];
    const float* enc    = (const float*)d_in[3];
    const float* emb    = (const float*)d_in[4];
    const float* Wih    = (const float*)d_in[5];
    const float* Whh    = (const float*)d_in[6];
    const float* bih    = (const float*)d_in[7];
    const float* bhh    = (const float*)d_in[8];
    const float* attnW  = (const float*)d_in[9];
    /* attnb (d_in[10]) unused: softmax shift-invariance */
    const float* outW   = (const float*)d_in[11];
    const float* outb   = (const float*)d_in[12];

    float* out = (float*)d_out;
    float* o_logsm = out;
    float* o_h     = out + V;
    float* o_c     = out + V + H;
    float* o_attn  = out + V + 2 * H;

    // high-priority side stream + fork/join events
    int loPri, hiPri;
    cudaDeviceGetStreamPriorityRange(&loPri, &hiPri);
    cudaStream_t s2;
    cudaStreamCreateWithPriority(&s2, cudaStreamNonBlocking, hiPri);
    cudaEvent_t eFork, eJoin;
    cudaEventCreateWithFlags(&eFork, cudaEventDisableTiming);
    cudaEventCreateWithFlags(&eJoin, cudaEventDisableTiming);

    k_gates <<<GATES_BLOCKS, 256>>>(word, emb, h0, c0, Wih, Whh, bih, bhh, o_h, o_c);
    cudaEventRecord(eFork, 0);

    // side stream (high priority): h-half of the big matvec
    cudaStreamWaitEvent(s2, eFork, 0);
    k_logits_h<<<LOGITS_BLOCKS, 256, 0, s2>>>(outW, outb);
    cudaEventRecord(eJoin, s2);

    // main stream: attention chain
    k_vpart <<<VPART_BLOCKS, 1024>>>(attnW);
    k_scores<<<SCORES_BLOCKS, 256>>>(enc);
    k_cpart <<<CPART_BLOCKS, 1024>>>(enc, o_attn);

    // join, then c-half + finish
    cudaStreamWaitEvent(0, eJoin, 0);
    k_logits_c<<<LOGITS_BLOCKS, 256>>>(outW);
    k_final <<<(V / 4 + 255) / 256, 256>>>(o_logsm);
}

// round 10
// speedup vs baseline: 1.3430x; 1.0215x over previous
#include <cuda_runtime.h>
#include <math.h>

#define H 1024
#define V 50257
#define S 4096

#define GATES_BLOCKS  512
#define VPART_BLOCKS  32
#define SCORES_BLOCKS 512
#define CPART_BLOCKS  128
#define LOGITS_BLOCKS 592              /* persistent: 4 per SM */
#define LOGITS_WARPS  (LOGITS_BLOCKS * 8)
#define PREFETCH_ROWS 8192             /* h-half rows prefetched into L2 (32 MB) */

// -------- scratch (device globals; zero-initialized) --------
__device__ float  g_gates[4 * H];
__device__ float  g_h[H];
__device__ float  g_vpart[VPART_BLOCKS * H];
__device__ float  g_v[H];
__device__ float  g_scores[S];
__device__ float2 g_smpart[SCORES_BLOCKS];
__device__ float  g_sm_m, g_sm_inv;
__device__ float  g_cpart[CPART_BLOCKS * H];
__device__ float  g_feat[2 * H];
__device__ float  g_logits[V];
__device__ float2 g_lsepart[LOGITS_BLOCKS];
__device__ float  g_lse;
__device__ float  g_sink;              // DCE guard for prefetch
__device__ unsigned g_cnt0, g_cnt1, g_cnt2, g_cnt3, g_cnt4;   // zero-init; wrap to 0 each replay

// K0: L2 prefetch of out_W h-half (rows [0,PREFETCH_ROWS), cols [0,H)).
// Runs on the side stream concurrently with k_gates; fills L2 via __ldcg.
__global__ void k_prefetch(const float* __restrict__ outW) {
    int lane = threadIdx.x & 31;
    int warp = (blockIdx.x * blockDim.x + threadIdx.x) >> 5;
    int nwarps = (gridDim.x * blockDim.x) >> 5;
    float4 acc = make_float4(0.f, 0.f, 0.f, 0.f);
    for (int r = warp; r < PREFETCH_ROWS; r += nwarps) {
        const float4* p = (const float4*)(outW + (size_t)r * (2 * H)) + lane;
#pragma unroll
        for (int k = 0; k < 8; ++k) {
            float4 v = __ldcg(p + 32 * k);
            acc.x += v.x; acc.y += v.y; acc.z += v.z; acc.w += v.w;
        }
    }
    float s = acc.x + acc.y + acc.z + acc.w;
    if (s != s) g_sink = s;   // never true for finite inputs; defeats DCE
}

// K1: gates = W_ih·x + W_hh·h0 + biases; last block does the LSTM pointwise.
__global__ void k_gates(const int* __restrict__ word,
                        const float* __restrict__ emb,
                        const float* __restrict__ h0,
                        const float* __restrict__ c0,
                        const float* __restrict__ Wih,
                        const float* __restrict__ Whh,
                        const float* __restrict__ bih,
                        const float* __restrict__ bhh,
                        float* __restrict__ out_h,
                        float* __restrict__ out_c) {
    __shared__ float sx[H];
    __shared__ float sh[H];
    __shared__ bool  s_last;
    int tid = threadIdx.x;
    int w = word[0];
    for (int i = tid; i < H; i += 256) {
        sx[i] = emb[(size_t)w * H + i];
        sh[i] = h0[i];
    }
    __syncthreads();
    int lane = tid & 31;
    int warp = tid >> 5;
    int row  = blockIdx.x * 8 + warp;   // < 4096 always
    const float4* wi = (const float4*)(Wih + (size_t)row * H) + lane;
    const float4* wh = (const float4*)(Whh + (size_t)row * H) + lane;
    const float4* x4 = (const float4*)sx + lane;
    const float4* h4 = (const float4*)sh + lane;
    float4 ea[8], eb[8];
#pragma unroll
    for (int k = 0; k < 8; ++k) { ea[k] = __ldcs(wi + 32 * k); eb[k] = __ldcs(wh + 32 * k); }
    float acc = 0.f;
#pragma unroll
    for (int k = 0; k < 8; ++k) {
        float4 b = x4[32 * k], d = h4[32 * k];
        acc += ea[k].x * b.x + ea[k].y * b.y + ea[k].z * b.z + ea[k].w * b.w;
        acc += eb[k].x * d.x + eb[k].y * d.y + eb[k].z * d.z + eb[k].w * d.w;
    }
#pragma unroll
    for (int o = 16; o; o >>= 1) acc += __shfl_xor_sync(0xffffffffu, acc, o);
    if (lane == 0) g_gates[row] = acc + bih[row] + bhh[row];

    __threadfence();
    __syncthreads();
    if (tid == 0) {
        unsigned t = atomicInc(&g_cnt0, GATES_BLOCKS - 1);
        s_last = (t == GATES_BLOCKS - 1);
    }
    __syncthreads();
    if (s_last) {
        for (int j = tid; j < H; j += 256) {
            float ig = g_gates[j];
            float fg = g_gates[H + j];
            float gg = g_gates[2 * H + j];
            float og = g_gates[3 * H + j];
            float si = 1.f / (1.f + expf(-ig));
            float sf = 1.f / (1.f + expf(-fg));
            float so = 1.f / (1.f + expf(-og));
            float cn = sf * c0[j] + si * tanhf(gg);
            float hn = so * tanhf(cn);
            g_h[j] = hn;
            g_feat[j] = hn;
            out_h[j] = hn;
            out_c[j] = cn;
        }
    }
}

// K2: v[k] = sum_j attn_W[j][k] * h[j].  grid 32 x 1024.
__global__ __launch_bounds__(1024, 1)
void k_vpart(const float* __restrict__ attnW) {
    __shared__ float  shh[32];
    __shared__ float4 spart[1024];
    __shared__ bool   s_last;
    int t = threadIdx.x;
    int c = t & 255;     // column chunk 0..255
    int g = t >> 8;      // row group 0..3
    int j0 = blockIdx.x * 32;
    if (t < 32) shh[t] = g_h[j0 + t];
    __syncthreads();
    const float4* base = (const float4*)attnW + (size_t)(j0 + g * 8) * (H / 4) + c;
    float4 e[8];
#pragma unroll
    for (int r = 0; r < 8; ++r) e[r] = base[(size_t)r * (H / 4)];
    float4 acc = make_float4(0.f, 0.f, 0.f, 0.f);
#pragma unroll
    for (int r = 0; r < 8; ++r) {
        float hv = shh[g * 8 + r];
        acc.x += e[r].x * hv; acc.y += e[r].y * hv;
        acc.z += e[r].z * hv; acc.w += e[r].w * hv;
    }
    spart[t] = acc;
    __syncthreads();
    if (g == 0) {
        float4 a = spart[c], b = spart[256 + c], d = spart[512 + c], f = spart[768 + c];
        a.x += b.x + d.x + f.x; a.y += b.y + d.y + f.y;
        a.z += b.z + d.z + f.z; a.w += b.w + d.w + f.w;
        ((float4*)(g_vpart + (size_t)blockIdx.x * H))[c] = a;
    }
    __threadfence();
    __syncthreads();
    if (t == 0) {
        unsigned cnt = atomicInc(&g_cnt1, VPART_BLOCKS - 1);
        s_last = (cnt == VPART_BLOCKS - 1);
    }
    __syncthreads();
    if (s_last) {
        const float4* p4 = (const float4*)g_vpart;
        float4 a = make_float4(0.f, 0.f, 0.f, 0.f);
#pragma unroll
        for (int b = 0; b < 8; ++b) {
            float4 e2 = p4[(size_t)(g * 8 + b) * (H / 4) + c];
            a.x += e2.x; a.y += e2.y; a.z += e2.z; a.w += e2.w;
        }
        spart[t] = a;
        __syncthreads();
        if (g == 0) {
            float4 x = spart[c], y = spart[256 + c], z = spart[512 + c], u = spart[768 + c];
            x.x += y.x + z.x + u.x; x.y += y.y + z.y + u.y;
            x.z += y.z + z.z + u.z; x.w += y.w + z.w + u.w;
            ((float4*)g_v)[c] = x;
        }
    }
}

// K3: scores[s] = enc[s]·v; per-block softmax partials; last block merges.
__global__ void k_scores(const float* __restrict__ enc) {
    __shared__ float sv[H];
    __shared__ float swarp[8];
    __shared__ bool  s_last;
    int tid = threadIdx.x;
    for (int i = tid; i < H; i += 256) sv[i] = g_v[i];
    __syncthreads();
    int lane = tid & 31;
    int warp = tid >> 5;
    int srow = blockIdx.x * 8 + warp;   // < 4096 always
    const float4* e4 = (const float4*)(enc + (size_t)srow * H) + lane;
    const float4* v4 = (const float4*)sv + lane;
    float4 e[8];
#pragma unroll
    for (int k = 0; k < 8; ++k) e[k] = e4[32 * k];
    float acc = 0.f;
#pragma unroll
    for (int k = 0; k < 8; ++k) {
        float4 b = v4[32 * k];
        acc += e[k].x * b.x + e[k].y * b.y + e[k].z * b.z + e[k].w * b.w;
    }
#pragma unroll
    for (int o = 16; o; o >>= 1) acc += __shfl_xor_sync(0xffffffffu, acc, o);
    if (lane == 0) { g_scores[srow] = acc; swarp[warp] = acc; }
    __syncthreads();
    if (tid == 0) {
        float m = swarp[0];
#pragma unroll
        for (int i = 1; i < 8; ++i) m = fmaxf(m, swarp[i]);
        float s = 0.f;
#pragma unroll
        for (int i = 0; i < 8; ++i) s += expf(swarp[i] - m);
        g_smpart[blockIdx.x] = make_float2(m, s);
    }
    __threadfence();
    __syncthreads();
    if (tid == 0) {
        unsigned c = atomicInc(&g_cnt2, SCORES_BLOCKS - 1);
        s_last = (c == SCORES_BLOCKS - 1);
    }
    __syncthreads();
    if (s_last) {
        __shared__ float rm[256];
        __shared__ float rs[256];
        float2 p0 = g_smpart[tid];
        float2 p1 = g_smpart[tid + 256];
        float m = fmaxf(p0.x, p1.x);
        float s = p0.y * expf(p0.x - m) + p1.y * expf(p1.x - m);
        rm[tid] = m; rs[tid] = s;
        __syncthreads();
        for (int o = 128; o; o >>= 1) {
            if (tid < o) {
                float m2 = rm[tid + o], s2 = rs[tid + o];
                float mn = fmaxf(rm[tid], m2);
                rs[tid] = rs[tid] * expf(rm[tid] - mn) + s2 * expf(m2 - mn);
                rm[tid] = mn;
            }
            __syncthreads();
        }
        if (tid == 0) { g_sm_m = rm[0]; g_sm_inv = 1.f / rs[0]; }
    }
}

// K4: attn normalize + context partials.  grid 128 x 1024.
__global__ __launch_bounds__(1024, 1)
void k_cpart(const float* __restrict__ enc,
             float* __restrict__ out_attn) {
    __shared__ float  sat[32];
    __shared__ float4 spart[1024];
    __shared__ bool   s_last;
    int t = threadIdx.x;
    int c = t & 255;
    int g = t >> 8;
    int s0 = blockIdx.x * 32;
    if (t < 32) {
        float a = expf(g_scores[s0 + t] - g_sm_m) * g_sm_inv;
        sat[t] = a;
        out_attn[s0 + t] = a;
    }
    __syncthreads();
    const float4* base = (const float4*)enc + (size_t)(s0 + g * 8) * (H / 4) + c;
    float4 e[8];
#pragma unroll
    for (int r = 0; r < 8; ++r) e[r] = base[(size_t)r * (H / 4)];
    float4 acc = make_float4(0.f, 0.f, 0.f, 0.f);
#pragma unroll
    for (int r = 0; r < 8; ++r) {
        float aw = sat[g * 8 + r];
        acc.x += e[r].x * aw; acc.y += e[r].y * aw;
        acc.z += e[r].z * aw; acc.w += e[r].w * aw;
    }
    spart[t] = acc;
    __syncthreads();
    if (g == 0) {
        float4 a = spart[c], b = spart[256 + c], d = spart[512 + c], f = spart[768 + c];
        a.x += b.x + d.x + f.x; a.y += b.y + d.y + f.y;
        a.z += b.z + d.z + f.z; a.w += b.w + d.w + f.w;
        ((float4*)(g_cpart + (size_t)blockIdx.x * H))[c] = a;
    }
    __threadfence();
    __syncthreads();
    if (t == 0) {
        unsigned cnt = atomicInc(&g_cnt3, CPART_BLOCKS - 1);
        s_last = (cnt == CPART_BLOCKS - 1);
    }
    __syncthreads();
    if (s_last) {
        const float4* p4 = (const float4*)g_cpart;
        float4 a = make_float4(0.f, 0.f, 0.f, 0.f);
#pragma unroll 8
        for (int b = 0; b < 32; ++b) {
            float4 e2 = p4[(size_t)(g * 32 + b) * (H / 4) + c];
            a.x += e2.x; a.y += e2.y; a.z += e2.z; a.w += e2.w;
        }
        spart[t] = a;
        __syncthreads();
        if (g == 0) {
            float4 x = spart[c], y = spart[256 + c], z = spart[512 + c], u = spart[768 + c];
            x.x += y.x + z.x + u.x; x.y += y.y + z.y + u.y;
            x.z += y.z + z.z + u.z; x.w += y.w + z.w + u.w;
            ((float4*)g_feat)[(H / 4) + c] = x;
        }
    }
}

// K5a: logits h-half: g_logits[r] = out_W[r, 0:H]·h + out_b[r].
// Persistent grid-stride, 4 blocks/SM, 8-deep streaming loads.
__global__ __launch_bounds__(256, 4)
void k_logits_h(const float* __restrict__ outW,
                const float* __restrict__ outb) {
    __shared__ float sf[H];
    int tid  = threadIdx.x;
    int lane = tid & 31;
    int warp = tid >> 5;
    for (int i = tid; i < H; i += 256) sf[i] = g_h[i];
    __syncthreads();
    const float4* f4 = (const float4*)sf + lane;
    for (int r = blockIdx.x * 8 + warp; r < V; r += LOGITS_WARPS) {
        const float4* wa = (const float4*)(outW + (size_t)r * (2 * H)) + lane;
        float4 A[8];
#pragma unroll
        for (int k = 0; k < 8; ++k) A[k] = __ldcs(wa + 32 * k);
        float acc = 0.f;
#pragma unroll
        for (int k = 0; k < 8; ++k) {
            float4 b = f4[32 * k];
            acc += A[k].x * b.x + A[k].y * b.y + A[k].z * b.z + A[k].w * b.w;
        }
#pragma unroll
        for (int o = 16; o; o >>= 1) acc += __shfl_xor_sync(0xffffffffu, acc, o);
        if (lane == 0) g_logits[r] = acc + outb[r];
    }
}

// K5b: logits c-half: g_logits[r] += out_W[r, H:2H]·context; online LSE;
// last block merges LOGITS_BLOCKS partials.
__global__ __launch_bounds__(256, 4)
void k_logits_c(const float* __restrict__ outW) {
    __shared__ float  sf[H];
    __shared__ float2 swarp[8];
    __shared__ bool   s_last;
    int tid  = threadIdx.x;
    int lane = tid & 31;
    int warp = tid >> 5;
    for (int i = tid; i < H; i += 256) sf[i] = g_feat[H + i];
    __syncthreads();
    const float4* f4 = (const float4*)sf + lane;
    float wm = -INFINITY, ws = 0.f;   // per-warp (lane0-valid) online LSE
    for (int r = blockIdx.x * 8 + warp; r < V; r += LOGITS_WARPS) {
        const float4* wa = (const float4*)(outW + (size_t)r * (2 * H) + H) + lane;
        float4 A[8];
#pragma unroll
        for (int k = 0; k < 8; ++k) A[k] = __ldcs(wa + 32 * k);
        float acc = 0.f;
#pragma unroll
        for (int k = 0; k < 8; ++k) {
            float4 b = f4[32 * k];
            acc += A[k].x * b.x + A[k].y * b.y + A[k].z * b.z + A[k].w * b.w;
        }
#pragma unroll
        for (int o = 16; o; o >>= 1) acc += __shfl_xor_sync(0xffffffffu, acc, o);
        if (lane == 0) {
            float v = g_logits[r] + acc;
            g_logits[r] = v;
            float mn = fmaxf(wm, v);
            ws = ws * expf(wm - mn) + expf(v - mn);
            wm = mn;
        }
    }

    if (lane == 0) swarp[warp] = make_float2(wm, ws);
    __syncthreads();
    if (tid == 0) {
        float m = -INFINITY, s = 0.f;
#pragma unroll
        for (int i = 0; i < 8; ++i) {
            float2 p = swarp[i];
            float mn = fmaxf(m, p.x);
            s = s * expf(m - mn) + p.y * expf(p.x - mn);
            m = mn;
        }
        g_lsepart[blockIdx.x] = make_float2(m, s);
    }
    __threadfence();
    __syncthreads();
    if (tid == 0) {
        unsigned c = atomicInc(&g_cnt4, LOGITS_BLOCKS - 1);
        s_last = (c == LOGITS_BLOCKS - 1);
    }
    __syncthreads();
    if (s_last) {
        __shared__ float rm[256];
        __shared__ float rs[256];
        float m = -INFINITY, s = 0.f;
        for (int i = tid; i < LOGITS_BLOCKS; i += 256) {   // fixed order per thread
            float2 p = g_lsepart[i];
            float mn = fmaxf(m, p.x);
            s = s * expf(m - mn) + p.y * expf(p.x - mn);
            m = mn;
        }
        rm[tid] = m; rs[tid] = s;
        __syncthreads();
        for (int o = 128; o; o >>= 1) {
            if (tid < o) {
                float m2 = rm[tid + o], s2 = rs[tid + o];
                float mn = fmaxf(rm[tid], m2);
                rs[tid] = rs[tid] * expf(rm[tid] - mn) + s2 * expf(m2 - mn);
                rm[tid] = mn;
            }
            __syncthreads();
        }
        if (tid == 0) g_lse = rm[0] + logf(rs[0]);
    }
}

// K6: final log-softmax write (float4; V = 4*12564 + 1).
__global__ void k_final(float* __restrict__ out) {
    int t = blockIdx.x * 256 + threadIdx.x;
    float lse = g_lse;
    if (t < V / 4) {
        float4 v = ((const float4*)g_logits)[t];
        v.x -= lse; v.y -= lse; v.z -= lse; v.w -= lse;
        ((float4*)out)[t] = v;
    }
    if (t == 0) out[V - 1] = g_logits[V - 1] - lse;
}

extern "C" void kernel_launch(void* const* d_in, const int* in_sizes, int n_in,
                              void* d_out, int out_size) {
    const int*   word   = (const int*)  d_in[0];
    const float* h0     = (const float*)d_in[1];
    const float* c0     = (const float*)d_in[2];
    const float* enc    = (const float*)d_in[3];
    const float* emb    = (const float*)d_in[4];
    const float* Wih    = (const float*)d_in[5];
    const float* Whh    = (const float*)d_in[6];
    const float* bih    = (const float*)d_in[7];
    const float* bhh    = (const float*)d_in[8];
    const float* attnW  = (const float*)d_in[9];
    /* attnb (d_in[10]) unused: softmax shift-invariance */
    const float* outW   = (const float*)d_in[11];
    const float* outb   = (const float*)d_in[12];

    float* out = (float*)d_out;
    float* o_logsm = out;
    float* o_h     = out + V;
    float* o_c     = out + V + H;
    float* o_attn  = out + V + 2 * H;

    // high-priority side stream + fork/join events
    int loPri, hiPri;
    cudaDeviceGetStreamPriorityRange(&loPri, &hiPri);
    cudaStream_t s2;
    cudaStreamCreateWithPriority(&s2, cudaStreamNonBlocking, hiPri);
    cudaEvent_t eFork, eJoin;
    cudaEventCreateWithFlags(&eFork, cudaEventDisableTiming);
    cudaEventCreateWithFlags(&eJoin, cudaEventDisableTiming);

    // side stream: prefetch out_W h-half into L2 concurrently with gates
    k_prefetch<<<148, 256, 0, s2>>>(outW);

    k_gates <<<GATES_BLOCKS, 256>>>(word, emb, h0, c0, Wih, Whh, bih, bhh, o_h, o_c);
    cudaEventRecord(eFork, 0);

    // side stream (high priority): h-half of the big matvec (after prefetch, after gates)
    cudaStreamWaitEvent(s2, eFork, 0);
    k_logits_h<<<LOGITS_BLOCKS, 256, 0, s2>>>(outW, outb);
    cudaEventRecord(eJoin, s2);

    // main stream: attention chain (hidden under logits_h)
    k_vpart <<<VPART_BLOCKS, 1024>>>(attnW);
    k_scores<<<SCORES_BLOCKS, 256>>>(enc);
    k_cpart <<<CPART_BLOCKS, 1024>>>(enc, o_attn);

    // join, then c-half + finish
    cudaStreamWaitEvent(0, eJoin, 0);
    k_logits_c<<<LOGITS_BLOCKS, 256>>>(outW);
    k_final <<<(V / 4 + 255) / 256, 256>>>(o_logsm);
}